// round 13
// baseline (speedup 1.0000x reference)
#include <cuda_runtime.h>
#include <cuda_bf16.h>
#include <mma.h>
#include <math.h>
#include <stdint.h>

using namespace nvcuda;

#define TT 8192
#define IN_DIM 2048
#define OUT_DIM 2048
#define PROJ 512
#define NE 8
#define NSLOT (TT * 2)
#define PADROWS (NSLOT + NE * 128)   // 17408
#define MAXTILES (PADROWS / 128)     // 136
#define NBUCK 64                     // bucket blocks (64*256 == NSLOT)

#define APAD 24     // sA row stride (elements)
#define BPAD 136    // sB row stride (elements)
// dynamic smem stage layout (bytes)
#define OFF_AL 6144
#define OFF_BH 12288
#define OFF_BL 16640
#define STG 20992
#define NSTAGE 4
#define SOFF_TOK (NSTAGE * STG)          // 83968
#define SOFF_BIAS (SOFF_TOK + 512)
#define SMEM_DYN (SOFF_BIAS + 512)       // 84992

// ---------------- device scratch ----------------
__device__ __align__(16) int   g_route_e[NSLOT];
__device__ __align__(16) float g_route_w[NSLOT];
__device__ __align__(16) int   g_bucket_slot[PADROWS];
__device__ __align__(16) int   g_pos[NSLOT];
__device__ __align__(16) int   g_tile_expert[MAXTILES];
__device__ __align__(16) int   g_tile_rowbase[MAXTILES];
__device__ __align__(16) int   g_localpos[NSLOT];
__device__ __align__(16) int   g_hist[NBUCK][8];
__device__ __align__(16) int   g_blockstart[NBUCK][8];
__device__ __align__(16) __nv_bfloat16 g_x_h[(size_t)TT * IN_DIM];
__device__ __align__(16) __nv_bfloat16 g_x_l[(size_t)TT * IN_DIM];
__device__ __align__(16) __nv_bfloat16 g_w1_h[(size_t)NE * IN_DIM * PROJ];
__device__ __align__(16) __nv_bfloat16 g_w1_l[(size_t)NE * IN_DIM * PROJ];
__device__ __align__(16) __nv_bfloat16 g_w2_h[(size_t)NE * PROJ * OUT_DIM];
__device__ __align__(16) __nv_bfloat16 g_w2_l[(size_t)NE * PROJ * OUT_DIM];
__device__ __align__(16) __nv_bfloat16 g_Hh[(size_t)PADROWS * PROJ];
__device__ __align__(16) __nv_bfloat16 g_Hl[(size_t)PADROWS * PROJ];
__device__ __align__(16) float g_Y[(size_t)PADROWS * OUT_DIM];

// ---------------- helpers ----------------
__device__ __forceinline__ void split2(float a, float b, uint32_t& h, uint32_t& l) {
    __nv_bfloat16 ah = __float2bfloat16(a), bh = __float2bfloat16(b);
    __nv_bfloat16 al = __float2bfloat16(a - __bfloat162float(ah));
    __nv_bfloat16 bl = __float2bfloat16(b - __bfloat162float(bh));
    h = (uint32_t)__bfloat16_as_ushort(ah) | ((uint32_t)__bfloat16_as_ushort(bh) << 16);
    l = (uint32_t)__bfloat16_as_ushort(al) | ((uint32_t)__bfloat16_as_ushort(bl) << 16);
}
__device__ __forceinline__ float gelu_f(float v) {
    const float c = 0.7978845608028654f;
    return 0.5f * v * (1.0f + tanhf(c * (v + 0.044715f * v * v * v)));
}
__device__ __forceinline__ uint32_t smem_u32(const void* p) {
    uint32_t a;
    asm("{ .reg .u64 t; cvta.to.shared.u64 t, %1; cvt.u32.u64 %0, t; }" : "=r"(a) : "l"(p));
    return a;
}
#define CP_ASYNC(dst, src, sz) \
    asm volatile("cp.async.cg.shared.global [%0], [%1], 16, %2;" \
                 :: "r"(dst), "l"(src), "r"(sz) : "memory")
#define CP_COMMIT() asm volatile("cp.async.commit_group;" ::: "memory")
#define CP_WAIT2() asm volatile("cp.async.wait_group 2;" ::: "memory")

// ---------------- 1. gating + x hi/lo split (R10 exact) ----------------
__global__ __launch_bounds__(256) void gating_kernel(
    const float* __restrict__ x, const float* __restrict__ gw,
    const float* __restrict__ gb) {
    int warp = threadIdx.x >> 5, lane = threadIdx.x & 31;
    int t = blockIdx.x * 8 + warp;
    const float* xr = x + (size_t)t * IN_DIM;
    __nv_bfloat16* xh = g_x_h + (size_t)t * IN_DIM;
    __nv_bfloat16* xl = g_x_l + (size_t)t * IN_DIM;
    float acc[8] = {};
    for (int i = lane; i < IN_DIM; i += 32) {
        float xv = xr[i];
        __nv_bfloat16 hh = __float2bfloat16(xv);
        xh[i] = hh;
        xl[i] = __float2bfloat16(xv - __bfloat162float(hh));
        const float4* g4 = (const float4*)(gw + (size_t)i * NE);
        float4 g0 = g4[0], g1 = g4[1];
        acc[0] += xv * g0.x; acc[1] += xv * g0.y; acc[2] += xv * g0.z; acc[3] += xv * g0.w;
        acc[4] += xv * g1.x; acc[5] += xv * g1.y; acc[6] += xv * g1.z; acc[7] += xv * g1.w;
    }
#pragma unroll
    for (int o = 16; o > 0; o >>= 1)
#pragma unroll
        for (int e = 0; e < 8; e++) acc[e] += __shfl_xor_sync(0xffffffffu, acc[e], o);
    if (lane == 0) {
        const float INV = 0.022097086912079608f;
        float l[8], m = -1e30f;
#pragma unroll
        for (int e = 0; e < 8; e++) { l[e] = (acc[e] + gb[e]) * INV; m = fmaxf(m, l[e]); }
        float p[8], s = 0.f;
#pragma unroll
        for (int e = 0; e < 8; e++) { p[e] = expf(l[e] - m); s += p[e]; }
        int i1 = 0;
#pragma unroll
        for (int e = 1; e < 8; e++) if (l[e] > l[i1]) i1 = e;
        int i2 = (i1 == 0) ? 1 : 0;
#pragma unroll
        for (int e = 0; e < 8; e++) if (e != i1 && l[e] > l[i2]) i2 = e;
        float inv_s = 1.f / s;
        g_route_e[2 * t] = i1;     g_route_w[2 * t] = p[i1] * inv_s;
        g_route_e[2 * t + 1] = i2; g_route_w[2 * t + 1] = p[i2] * inv_s;
    }
}

// ---------------- 2a. bucket histogram + local ranks (64 CTAs) ----------------
__global__ __launch_bounds__(256) void bucketA_kernel() {
    __shared__ int wcnt[8][8];    // [warp][expert]
    __shared__ int wbase[8][8];
    const int tid = threadIdx.x, lane = tid & 31, warp = tid >> 5;
    const int b = blockIdx.x;
    const int s = b * 256 + tid;
    for (int i = b * 256 + tid; i < PADROWS; i += NBUCK * 256) g_bucket_slot[i] = -1;
    const int e = g_route_e[s];
    int myrank = 0;
#pragma unroll
    for (int q = 0; q < 8; q++) {
        unsigned bal = __ballot_sync(0xffffffffu, e == q);
        if (e == q) myrank = __popc(bal & ((1u << lane) - 1u));
        if (lane == q) wcnt[warp][q] = __popc(bal);
    }
    __syncthreads();
    if (tid < 8) {
        int ee = tid, r = 0;
#pragma unroll
        for (int w = 0; w < 8; w++) { wbase[w][ee] = r; r += wcnt[w][ee]; }
        g_hist[b][ee] = r;
    }
    __syncthreads();
    g_localpos[s] = wbase[warp][e] + myrank;
}

// ---------------- 2b. cross-block scan + tile table (1 CTA) ----------------
__global__ __launch_bounds__(256) void bucketB_kernel() {
    __shared__ int pre[NBUCK][8];
    __shared__ int tot[8];
    __shared__ int base[8];
    __shared__ int tilebase[9];
    const int tid = threadIdx.x, lane = tid & 31, warp = tid >> 5;
    {
        const int q = warp;   // 8 warps, one expert each
        int carry = 0;
#pragma unroll
        for (int c = 0; c < NBUCK / 32; c++) {
            int v = g_hist[c * 32 + lane][q];
            int s = v;
#pragma unroll
            for (int o = 1; o < 32; o <<= 1) {
                int n = __shfl_up_sync(0xffffffffu, s, o);
                if (lane >= o) s += n;
            }
            pre[c * 32 + lane][q] = carry + s - v;
            carry += __shfl_sync(0xffffffffu, s, 31);
        }
        if (lane == 0) tot[q] = carry;
    }
    __syncthreads();
    if (tid == 0) {
        int p = 0, tb = 0;
        for (int e = 0; e < 8; e++) {
            base[e] = p;
            tilebase[e] = tb;
            int nt = (tot[e] + 127) >> 7;
            tb += nt;
            p += nt * 128;
        }
        tilebase[8] = tb;
    }
    __syncthreads();
    for (int idx = tid; idx < NBUCK * 8; idx += 256) {
        int b = idx >> 3, q = idx & 7;
        g_blockstart[b][q] = base[q] + pre[b][q];
    }
    for (int i = tid; i < MAXTILES; i += 256) {
        int e = -1;
#pragma unroll
        for (int q = 0; q < 8; q++)
            if (i >= tilebase[q] && i < tilebase[q + 1]) e = q;
        g_tile_expert[i] = e;
        g_tile_rowbase[i] = (e >= 0) ? base[e] + (i - tilebase[e]) * 128 : 0;
    }
}

// ---------------- 2c. scatter (64 CTAs) ----------------
__global__ __launch_bounds__(256) void bucketC_kernel() {
    const int s = blockIdx.x * 256 + threadIdx.x;
    const int e = g_route_e[s];
    const int p = g_blockstart[blockIdx.x][e] + g_localpos[s];
    g_bucket_slot[p] = s;
    g_pos[s] = p;
}

// ---------------- weight fp32 -> bf16 hi/lo split (R10 exact) ----------------
__global__ __launch_bounds__(256) void fsplit_kernel(const float* __restrict__ src, int which) {
    __nv_bfloat16 *dh, *dl;
    if (which == 1) { dh = g_w1_h; dl = g_w1_l; }
    else            { dh = g_w2_h; dl = g_w2_l; }
    size_t i = (size_t)blockIdx.x * 256 + threadIdx.x;   // per 4 floats
    float4 v = ((const float4*)src)[i];
    uint32_t h0, l0, h1, l1;
    split2(v.x, v.y, h0, l0);
    split2(v.z, v.w, h1, l1);
    ((uint2*)dh)[i] = make_uint2(h0, h1);
    ((uint2*)dl)[i] = make_uint2(l0, l1);
}

// ---------------- wmma GEMM: 8 warps, 32x64 warp tile, 4-stage cp.async ring ----------------
template <int KTOT, bool IS_G1>
__global__ __launch_bounds__(256, 2) void gemm_wmma_kernel(const float* __restrict__ bias) {
    constexpr int NC = KTOT / 16;
    constexpr int NDIM = IS_G1 ? PROJ : OUT_DIM;
    extern __shared__ __align__(16) char smx[];
    int* tokS = (int*)(smx + SOFF_TOK);
    float* biasS = (float*)(smx + SOFF_BIAS);

    const int e = g_tile_expert[blockIdx.x];
    if (e < 0) return;
    const int rowbase = g_tile_rowbase[blockIdx.x];
    const int n0 = blockIdx.y * 128;
    const int tid = threadIdx.x, lane = tid & 31, warp = tid >> 5;
    const int wm = warp >> 1, wn = warp & 1;   // warp tile: 32m x 64n
    const uint32_t sbase = smem_u32(smx);

    if (tid < 128) {
        int slot = g_bucket_slot[rowbase + tid];
        tokS[tid] = IS_G1 ? (slot >= 0 ? (slot >> 1) : -1) : slot;
        biasS[tid] = bias[(size_t)e * NDIM + n0 + tid];
    }
    __syncthreads();

    // loader geometry
    const int lr = tid >> 1, lc8 = (tid & 1) * 8;
    const int bk = tid >> 4, bn8 = (tid & 15) * 8;
    const __nv_bfloat16 *pAh, *pAl;
    uint32_t valA = 16;
    if (IS_G1) {
        int tok = tokS[lr];
        if (tok < 0) { valA = 0; tok = 0; }
        pAh = g_x_h + (size_t)tok * IN_DIM + lc8;
        pAl = g_x_l + (size_t)tok * IN_DIM + lc8;
    } else {
        pAh = g_Hh + (size_t)(rowbase + lr) * PROJ + lc8;
        pAl = g_Hl + (size_t)(rowbase + lr) * PROJ + lc8;
    }
    const __nv_bfloat16* Wh = IS_G1 ? g_w1_h : g_w2_h;
    const __nv_bfloat16* Wl = IS_G1 ? g_w1_l : g_w2_l;
    const __nv_bfloat16* pBh = Wh + ((size_t)e * KTOT + bk) * NDIM + n0 + bn8;
    const __nv_bfloat16* pBl = Wl + ((size_t)e * KTOT + bk) * NDIM + n0 + bn8;

    const uint32_t offA = (uint32_t)(lr * APAD + lc8) * 2;
    const uint32_t offB = (uint32_t)(bk * BPAD + bn8) * 2;

#define ISSUE(kidx)                                                         \
    do {                                                                    \
        const uint32_t _s = sbase + (uint32_t)((kidx) & 3) * STG;           \
        const size_t _ka = (size_t)(kidx) * 16;                             \
        CP_ASYNC(_s + offA, pAh + _ka, valA);                               \
        CP_ASYNC(_s + OFF_AL + offA, pAl + _ka, valA);                      \
        CP_ASYNC(_s + OFF_BH + offB, pBh + _ka * NDIM, 16);                 \
        CP_ASYNC(_s + OFF_BL + offB, pBl + _ka * NDIM, 16);                 \
        CP_COMMIT();                                                        \
    } while (0)

    wmma::fragment<wmma::accumulator, 16, 16, 16, float> facc[2][4];
#pragma unroll
    for (int mi = 0; mi < 2; mi++)
#pragma unroll
        for (int ng = 0; ng < 4; ng++) wmma::fill_fragment(facc[mi][ng], 0.f);

    ISSUE(0);
    ISSUE(1);
    ISSUE(2);

#pragma unroll 1
    for (int k = 0; k < NC; k++) {
        CP_WAIT2();               // stage k complete (≤2 younger groups pending)
        __syncthreads();          // readers of buffer (k+3)&3 = (k-1)&3 finished at iter k-1
        if (k + 3 < NC) { ISSUE(k + 3); } else { CP_COMMIT(); }

        char* bufp = smx + (k & 3) * STG;
        wmma::fragment<wmma::matrix_a, 16, 16, 16, __nv_bfloat16, wmma::row_major> fah[2], fal[2];
#pragma unroll
        for (int mi = 0; mi < 2; mi++) {
            const int ar = wm * 32 + mi * 16;
            wmma::load_matrix_sync(fah[mi], (__nv_bfloat16*)bufp + ar * APAD, APAD);
            wmma::load_matrix_sync(fal[mi], (__nv_bfloat16*)(bufp + OFF_AL) + ar * APAD, APAD);
        }
#pragma unroll
        for (int ng = 0; ng < 4; ng++) {
            wmma::fragment<wmma::matrix_b, 16, 16, 16, __nv_bfloat16, wmma::row_major> fbh, fbl;
            const int bc = wn * 64 + ng * 16;
            wmma::load_matrix_sync(fbh, (__nv_bfloat16*)(bufp + OFF_BH) + bc, BPAD);
            wmma::load_matrix_sync(fbl, (__nv_bfloat16*)(bufp + OFF_BL) + bc, BPAD);
#pragma unroll
            for (int mi = 0; mi < 2; mi++) {
                wmma::mma_sync(facc[mi][ng], fah[mi], fbh, facc[mi][ng]);
                wmma::mma_sync(facc[mi][ng], fal[mi], fbh, facc[mi][ng]);
                wmma::mma_sync(facc[mi][ng], fah[mi], fbl, facc[mi][ng]);
            }
        }
    }

    // ---- epilogue: reuse smem as per-warp patch buffer ----
    __syncthreads();
    float* pw = (float*)smx + warp * 256;
#pragma unroll
    for (int mi = 0; mi < 2; mi++)
#pragma unroll
        for (int ng = 0; ng < 4; ng++) {
            __syncwarp();
            wmma::store_matrix_sync(pw, facc[mi][ng], 16, wmma::mem_row_major);
            __syncwarp();
            const int r = lane >> 1;               // 0..15
            const int c0 = (lane & 1) * 8;         // 0 or 8
            const int mloc = wm * 32 + mi * 16 + r;
            const size_t grow = (size_t)rowbase + mloc;
            const int lcol = wn * 64 + ng * 16 + c0;
            if (IS_G1) {
                float v[8];
#pragma unroll
                for (int j = 0; j < 8; j++)
                    v[j] = gelu_f(pw[r * 16 + c0 + j] + biasS[lcol + j]);
                uint32_t h[4], l[4];
#pragma unroll
                for (int q = 0; q < 4; q++) split2(v[2 * q], v[2 * q + 1], h[q], l[q]);
                *(uint4*)(g_Hh + grow * PROJ + n0 + lcol) = make_uint4(h[0], h[1], h[2], h[3]);
                *(uint4*)(g_Hl + grow * PROJ + n0 + lcol) = make_uint4(l[0], l[1], l[2], l[3]);
            } else {
                const int slot = tokS[mloc];
                if (slot >= 0) {
                    const float w = g_route_w[slot];
                    float* dst = g_Y + grow * OUT_DIM + n0 + lcol;
#pragma unroll
                    for (int j = 0; j < 8; j++)
                        dst[j] = w * (pw[r * 16 + c0 + j] + biasS[lcol + j]);
                }
            }
        }
#undef ISSUE
}

// ---------------- combine (validated) ----------------
__global__ __launch_bounds__(256) void combine_kernel(float* __restrict__ out) {
    int idx = blockIdx.x * 256 + threadIdx.x;
    int t = idx >> 9;
    int c = idx & 511;
    int p0 = g_pos[2 * t], p1 = g_pos[2 * t + 1];
    float4 a = ((const float4*)(g_Y + (size_t)p0 * OUT_DIM))[c];
    float4 b = ((const float4*)(g_Y + (size_t)p1 * OUT_DIM))[c];
    ((float4*)out)[idx] = make_float4(a.x + b.x, a.y + b.y, a.z + b.z, a.w + b.w);
}

extern "C" void kernel_launch(void* const* d_in, const int* in_sizes, int n_in,
                              void* d_out, int out_size) {
    const float* x      = (const float*)d_in[0];
    const float* gate_w = (const float*)d_in[1];
    const float* gate_b = (const float*)d_in[2];
    const float* w1     = (const float*)d_in[3];
    const float* b1     = (const float*)d_in[4];
    const float* w2     = (const float*)d_in[5];
    const float* b2     = (const float*)d_in[6];
    float* out = (float*)d_out;

    cudaFuncSetAttribute(gemm_wmma_kernel<IN_DIM, true>,
                         cudaFuncAttributeMaxDynamicSharedMemorySize, SMEM_DYN);
    cudaFuncSetAttribute(gemm_wmma_kernel<PROJ, false>,
                         cudaFuncAttributeMaxDynamicSharedMemorySize, SMEM_DYN);

    gating_kernel<<<TT / 8, 256>>>(x, gate_w, gate_b);
    fsplit_kernel<<<((size_t)NE * IN_DIM * PROJ / 4) / 256, 256>>>(w1, 1);
    fsplit_kernel<<<((size_t)NE * PROJ * OUT_DIM / 4) / 256, 256>>>(w2, 2);
    bucketA_kernel<<<NBUCK, 256>>>();
    bucketB_kernel<<<1, 256>>>();
    bucketC_kernel<<<NBUCK, 256>>>();
    gemm_wmma_kernel<IN_DIM, true><<<dim3(MAXTILES, PROJ / 128), 256, SMEM_DYN>>>(b1);
    gemm_wmma_kernel<PROJ, false><<<dim3(MAXTILES, OUT_DIM / 128), 256, SMEM_DYN>>>(b2);
    combine_kernel<<<(TT * (OUT_DIM / 4)) / 256, 256>>>(out);
}

// round 14
// speedup vs baseline: 1.3929x; 1.3929x over previous
#include <cuda_runtime.h>
#include <cuda_bf16.h>
#include <mma.h>
#include <math.h>
#include <stdint.h>

using namespace nvcuda;

#define TT 8192
#define IN_DIM 2048
#define OUT_DIM 2048
#define PROJ 512
#define NE 8
#define NSLOT (TT * 2)
#define PADROWS (NSLOT + NE * 128)   // 17408
#define MAXTILES (PADROWS / 128)     // 136
#define NBUCK 64                     // bucket blocks (64*256 == NSLOT)

#define APAD 24     // sA row stride (elements)
#define BPAD 136    // sB row stride (elements)
// dynamic smem stage layout (bytes)
#define OFF_AL 6144
#define OFF_BH 12288
#define OFF_BL 16640
#define STG 20992
#define NSTAGE 3
#define SOFF_TOK (NSTAGE * STG)          // 62976
#define SOFF_BIAS (SOFF_TOK + 512)
#define SMEM_DYN (SOFF_BIAS + 512)       // 64000

// ---------------- device scratch ----------------
__device__ __align__(16) int   g_route_e[NSLOT];
__device__ __align__(16) float g_route_w[NSLOT];
__device__ __align__(16) int   g_bucket_slot[PADROWS];
__device__ __align__(16) int   g_tile_expert[MAXTILES];
__device__ __align__(16) int   g_tile_rowbase[MAXTILES];
__device__ __align__(16) int   g_localpos[NSLOT];
__device__ __align__(16) int   g_hist[NBUCK][8];
__device__ __align__(16) int   g_blockstart[NBUCK][8];
__device__ __align__(16) __nv_bfloat16 g_x_h[(size_t)TT * IN_DIM];
__device__ __align__(16) __nv_bfloat16 g_x_l[(size_t)TT * IN_DIM];
__device__ __align__(16) __nv_bfloat16 g_w1_h[(size_t)NE * IN_DIM * PROJ];
__device__ __align__(16) __nv_bfloat16 g_w1_l[(size_t)NE * IN_DIM * PROJ];
__device__ __align__(16) __nv_bfloat16 g_w2_h[(size_t)NE * PROJ * OUT_DIM];
__device__ __align__(16) __nv_bfloat16 g_w2_l[(size_t)NE * PROJ * OUT_DIM];
__device__ __align__(16) __nv_bfloat16 g_Hh[(size_t)PADROWS * PROJ];
__device__ __align__(16) __nv_bfloat16 g_Hl[(size_t)PADROWS * PROJ];

// ---------------- helpers ----------------
__device__ __forceinline__ void split2(float a, float b, uint32_t& h, uint32_t& l) {
    __nv_bfloat16 ah = __float2bfloat16(a), bh = __float2bfloat16(b);
    __nv_bfloat16 al = __float2bfloat16(a - __bfloat162float(ah));
    __nv_bfloat16 bl = __float2bfloat16(b - __bfloat162float(bh));
    h = (uint32_t)__bfloat16_as_ushort(ah) | ((uint32_t)__bfloat16_as_ushort(bh) << 16);
    l = (uint32_t)__bfloat16_as_ushort(al) | ((uint32_t)__bfloat16_as_ushort(bl) << 16);
}
__device__ __forceinline__ float gelu_f(float v) {
    const float c = 0.7978845608028654f;
    return 0.5f * v * (1.0f + tanhf(c * (v + 0.044715f * v * v * v)));
}
__device__ __forceinline__ uint32_t smem_u32(const void* p) {
    uint32_t a;
    asm("{ .reg .u64 t; cvta.to.shared.u64 t, %1; cvt.u32.u64 %0, t; }" : "=r"(a) : "l"(p));
    return a;
}
#define CP_ASYNC(dst, src, sz) \
    asm volatile("cp.async.cg.shared.global [%0], [%1], 16, %2;" \
                 :: "r"(dst), "l"(src), "r"(sz) : "memory")
#define CP_COMMIT() asm volatile("cp.async.commit_group;" ::: "memory")
#define CP_WAIT1() asm volatile("cp.async.wait_group 1;" ::: "memory")

// ---------------- 1. gating + x hi/lo split (R10 exact) ----------------
__global__ __launch_bounds__(256) void gating_kernel(
    const float* __restrict__ x, const float* __restrict__ gw,
    const float* __restrict__ gb) {
    int warp = threadIdx.x >> 5, lane = threadIdx.x & 31;
    int t = blockIdx.x * 8 + warp;
    const float* xr = x + (size_t)t * IN_DIM;
    __nv_bfloat16* xh = g_x_h + (size_t)t * IN_DIM;
    __nv_bfloat16* xl = g_x_l + (size_t)t * IN_DIM;
    float acc[8] = {};
    for (int i = lane; i < IN_DIM; i += 32) {
        float xv = xr[i];
        __nv_bfloat16 hh = __float2bfloat16(xv);
        xh[i] = hh;
        xl[i] = __float2bfloat16(xv - __bfloat162float(hh));
        const float4* g4 = (const float4*)(gw + (size_t)i * NE);
        float4 g0 = g4[0], g1 = g4[1];
        acc[0] += xv * g0.x; acc[1] += xv * g0.y; acc[2] += xv * g0.z; acc[3] += xv * g0.w;
        acc[4] += xv * g1.x; acc[5] += xv * g1.y; acc[6] += xv * g1.z; acc[7] += xv * g1.w;
    }
#pragma unroll
    for (int o = 16; o > 0; o >>= 1)
#pragma unroll
        for (int e = 0; e < 8; e++) acc[e] += __shfl_xor_sync(0xffffffffu, acc[e], o);
    if (lane == 0) {
        const float INV = 0.022097086912079608f;
        float l[8], m = -1e30f;
#pragma unroll
        for (int e = 0; e < 8; e++) { l[e] = (acc[e] + gb[e]) * INV; m = fmaxf(m, l[e]); }
        float p[8], s = 0.f;
#pragma unroll
        for (int e = 0; e < 8; e++) { p[e] = expf(l[e] - m); s += p[e]; }
        int i1 = 0;
#pragma unroll
        for (int e = 1; e < 8; e++) if (l[e] > l[i1]) i1 = e;
        int i2 = (i1 == 0) ? 1 : 0;
#pragma unroll
        for (int e = 0; e < 8; e++) if (e != i1 && l[e] > l[i2]) i2 = e;
        float inv_s = 1.f / s;
        g_route_e[2 * t] = i1;     g_route_w[2 * t] = p[i1] * inv_s;
        g_route_e[2 * t + 1] = i2; g_route_w[2 * t + 1] = p[i2] * inv_s;
    }
}

// ---------------- 2a. bucket histogram + local ranks (64 CTAs) ----------------
__global__ __launch_bounds__(256) void bucketA_kernel() {
    __shared__ int wcnt[8][8];    // [warp][expert]
    __shared__ int wbase[8][8];
    const int tid = threadIdx.x, lane = tid & 31, warp = tid >> 5;
    const int b = blockIdx.x;
    const int s = b * 256 + tid;
    for (int i = b * 256 + tid; i < PADROWS; i += NBUCK * 256) g_bucket_slot[i] = -1;
    const int e = g_route_e[s];
    int myrank = 0;
#pragma unroll
    for (int q = 0; q < 8; q++) {
        unsigned bal = __ballot_sync(0xffffffffu, e == q);
        if (e == q) myrank = __popc(bal & ((1u << lane) - 1u));
        if (lane == q) wcnt[warp][q] = __popc(bal);
    }
    __syncthreads();
    if (tid < 8) {
        int ee = tid, r = 0;
#pragma unroll
        for (int w = 0; w < 8; w++) { wbase[w][ee] = r; r += wcnt[w][ee]; }
        g_hist[b][ee] = r;
    }
    __syncthreads();
    g_localpos[s] = wbase[warp][e] + myrank;
}

// ---------------- 2b. cross-block scan + tile table (1 CTA) ----------------
__global__ __launch_bounds__(256) void bucketB_kernel() {
    __shared__ int pre[NBUCK][8];
    __shared__ int tot[8];
    __shared__ int base[8];
    __shared__ int tilebase[9];
    const int tid = threadIdx.x, lane = tid & 31, warp = tid >> 5;
    {
        const int q = warp;   // 8 warps, one expert each
        int carry = 0;
#pragma unroll
        for (int c = 0; c < NBUCK / 32; c++) {
            int v = g_hist[c * 32 + lane][q];
            int s = v;
#pragma unroll
            for (int o = 1; o < 32; o <<= 1) {
                int n = __shfl_up_sync(0xffffffffu, s, o);
                if (lane >= o) s += n;
            }
            pre[c * 32 + lane][q] = carry + s - v;
            carry += __shfl_sync(0xffffffffu, s, 31);
        }
        if (lane == 0) tot[q] = carry;
    }
    __syncthreads();
    if (tid == 0) {
        int p = 0, tb = 0;
        for (int e = 0; e < 8; e++) {
            base[e] = p;
            tilebase[e] = tb;
            int nt = (tot[e] + 127) >> 7;
            tb += nt;
            p += nt * 128;
        }
        tilebase[8] = tb;
    }
    __syncthreads();
    for (int idx = tid; idx < NBUCK * 8; idx += 256) {
        int b = idx >> 3, q = idx & 7;
        g_blockstart[b][q] = base[q] + pre[b][q];
    }
    for (int i = tid; i < MAXTILES; i += 256) {
        int e = -1;
#pragma unroll
        for (int q = 0; q < 8; q++)
            if (i >= tilebase[q] && i < tilebase[q + 1]) e = q;
        g_tile_expert[i] = e;
        g_tile_rowbase[i] = (e >= 0) ? base[e] + (i - tilebase[e]) * 128 : 0;
    }
}

// ---------------- 2c. scatter (64 CTAs) ----------------
__global__ __launch_bounds__(256) void bucketC_kernel() {
    const int s = blockIdx.x * 256 + threadIdx.x;
    const int e = g_route_e[s];
    const int p = g_blockstart[blockIdx.x][e] + g_localpos[s];
    g_bucket_slot[p] = s;
}

// ---------------- weight fp32 -> bf16 hi/lo split (R10 exact) ----------------
__global__ __launch_bounds__(256) void fsplit_kernel(const float* __restrict__ src, int which) {
    __nv_bfloat16 *dh, *dl;
    if (which == 1) { dh = g_w1_h; dl = g_w1_l; }
    else            { dh = g_w2_h; dl = g_w2_l; }
    size_t i = (size_t)blockIdx.x * 256 + threadIdx.x;   // per 4 floats
    float4 v = ((const float4*)src)[i];
    uint32_t h0, l0, h1, l1;
    split2(v.x, v.y, h0, l0);
    split2(v.z, v.w, h1, l1);
    ((uint2*)dh)[i] = make_uint2(h0, h1);
    ((uint2*)dl)[i] = make_uint2(l0, l1);
}

// ---------------- out zero-init ----------------
__global__ __launch_bounds__(256) void zero_kernel(float* __restrict__ out) {
    size_t i = (size_t)blockIdx.x * 256 + threadIdx.x;
    ((float4*)out)[i] = make_float4(0.f, 0.f, 0.f, 0.f);
}

// ---------------- wmma GEMM (R10 exact core); gemm2 epilogue -> atomicAdd out ----------------
template <int KTOT, bool IS_G1>
__global__ __launch_bounds__(256, 2) void gemm_wmma_kernel(
    const float* __restrict__ bias, float* __restrict__ out) {
    constexpr int NC = KTOT / 16;
    constexpr int NDIM = IS_G1 ? PROJ : OUT_DIM;
    extern __shared__ __align__(16) char smx[];
    int* tokS = (int*)(smx + SOFF_TOK);
    float* biasS = (float*)(smx + SOFF_BIAS);

    const int e = g_tile_expert[blockIdx.x];
    if (e < 0) return;
    const int rowbase = g_tile_rowbase[blockIdx.x];
    const int n0 = blockIdx.y * 128;
    const int tid = threadIdx.x, lane = tid & 31, warp = tid >> 5;
    const int wm = warp >> 1, wn = warp & 1;   // warp tile: 32m x 64n
    const uint32_t sbase = smem_u32(smx);

    if (tid < 128) {
        int slot = g_bucket_slot[rowbase + tid];
        tokS[tid] = IS_G1 ? (slot >= 0 ? (slot >> 1) : -1) : slot;
        biasS[tid] = bias[(size_t)e * NDIM + n0 + tid];
    }
    __syncthreads();

    // loader geometry
    const int lr = tid >> 1, lc8 = (tid & 1) * 8;
    const int bk = tid >> 4, bn8 = (tid & 15) * 8;
    const __nv_bfloat16 *pAh, *pAl;
    uint32_t valA = 16;
    if (IS_G1) {
        int tok = tokS[lr];
        if (tok < 0) { valA = 0; tok = 0; }
        pAh = g_x_h + (size_t)tok * IN_DIM + lc8;
        pAl = g_x_l + (size_t)tok * IN_DIM + lc8;
    } else {
        pAh = g_Hh + (size_t)(rowbase + lr) * PROJ + lc8;
        pAl = g_Hl + (size_t)(rowbase + lr) * PROJ + lc8;
    }
    const __nv_bfloat16* Wh = IS_G1 ? g_w1_h : g_w2_h;
    const __nv_bfloat16* Wl = IS_G1 ? g_w1_l : g_w2_l;
    const __nv_bfloat16* pBh = Wh + ((size_t)e * KTOT + bk) * NDIM + n0 + bn8;
    const __nv_bfloat16* pBl = Wl + ((size_t)e * KTOT + bk) * NDIM + n0 + bn8;

    const uint32_t offA = (uint32_t)(lr * APAD + lc8) * 2;
    const uint32_t offB = (uint32_t)(bk * BPAD + bn8) * 2;

#define ISSUE(kidx)                                                         \
    do {                                                                    \
        const uint32_t _s = sbase + (uint32_t)((kidx) % 3) * STG;           \
        const size_t _ka = (size_t)(kidx) * 16;                             \
        CP_ASYNC(_s + offA, pAh + _ka, valA);                               \
        CP_ASYNC(_s + OFF_AL + offA, pAl + _ka, valA);                      \
        CP_ASYNC(_s + OFF_BH + offB, pBh + _ka * NDIM, 16);                 \
        CP_ASYNC(_s + OFF_BL + offB, pBl + _ka * NDIM, 16);                 \
        CP_COMMIT();                                                        \
    } while (0)

    wmma::fragment<wmma::accumulator, 16, 16, 16, float> facc[2][4];
#pragma unroll
    for (int mi = 0; mi < 2; mi++)
#pragma unroll
        for (int ng = 0; ng < 4; ng++) wmma::fill_fragment(facc[mi][ng], 0.f);

    ISSUE(0);
    ISSUE(1);

#pragma unroll 1
    for (int k = 0; k < NC; k++) {
        CP_WAIT1();               // stage k done (only stage k+1 may remain in flight)
        __syncthreads();          // everyone waited; readers of buffer (k+2)%3 are done
        if (k + 2 < NC) { ISSUE(k + 2); } else { CP_COMMIT(); }

        char* bufp = smx + (k % 3) * STG;
        wmma::fragment<wmma::matrix_a, 16, 16, 16, __nv_bfloat16, wmma::row_major> fah[2], fal[2];
#pragma unroll
        for (int mi = 0; mi < 2; mi++) {
            const int ar = wm * 32 + mi * 16;
            wmma::load_matrix_sync(fah[mi], (__nv_bfloat16*)bufp + ar * APAD, APAD);
            wmma::load_matrix_sync(fal[mi], (__nv_bfloat16*)(bufp + OFF_AL) + ar * APAD, APAD);
        }
#pragma unroll
        for (int ng = 0; ng < 4; ng++) {
            wmma::fragment<wmma::matrix_b, 16, 16, 16, __nv_bfloat16, wmma::row_major> fbh, fbl;
            const int bc = wn * 64 + ng * 16;
            wmma::load_matrix_sync(fbh, (__nv_bfloat16*)(bufp + OFF_BH) + bc, BPAD);
            wmma::load_matrix_sync(fbl, (__nv_bfloat16*)(bufp + OFF_BL) + bc, BPAD);
#pragma unroll
            for (int mi = 0; mi < 2; mi++) {
                wmma::mma_sync(facc[mi][ng], fah[mi], fbh, facc[mi][ng]);
                wmma::mma_sync(facc[mi][ng], fal[mi], fbh, facc[mi][ng]);
                wmma::mma_sync(facc[mi][ng], fah[mi], fbl, facc[mi][ng]);
            }
        }
    }

    // ---- epilogue: reuse smem as per-warp patch buffer ----
    __syncthreads();
    float* pw = (float*)smx + warp * 256;
#pragma unroll
    for (int mi = 0; mi < 2; mi++)
#pragma unroll
        for (int ng = 0; ng < 4; ng++) {
            __syncwarp();
            wmma::store_matrix_sync(pw, facc[mi][ng], 16, wmma::mem_row_major);
            __syncwarp();
            const int r = lane >> 1;               // 0..15
            const int c0 = (lane & 1) * 8;         // 0 or 8
            const int mloc = wm * 32 + mi * 16 + r;
            const size_t grow = (size_t)rowbase + mloc;
            const int lcol = wn * 64 + ng * 16 + c0;
            if (IS_G1) {
                float v[8];
#pragma unroll
                for (int j = 0; j < 8; j++)
                    v[j] = gelu_f(pw[r * 16 + c0 + j] + biasS[lcol + j]);
                uint32_t h[4], l[4];
#pragma unroll
                for (int q = 0; q < 4; q++) split2(v[2 * q], v[2 * q + 1], h[q], l[q]);
                *(uint4*)(g_Hh + grow * PROJ + n0 + lcol) = make_uint4(h[0], h[1], h[2], h[3]);
                *(uint4*)(g_Hl + grow * PROJ + n0 + lcol) = make_uint4(l[0], l[1], l[2], l[3]);
            } else {
                const int slot = tokS[mloc];
                if (slot >= 0) {
                    const float w = g_route_w[slot];
                    const int tok = slot >> 1;
                    float* dst = out + (size_t)tok * OUT_DIM + n0 + lcol;
#pragma unroll
                    for (int j = 0; j < 8; j++)
                        atomicAdd(dst + j, w * (pw[r * 16 + c0 + j] + biasS[lcol + j]));
                }
            }
        }
#undef ISSUE
}

extern "C" void kernel_launch(void* const* d_in, const int* in_sizes, int n_in,
                              void* d_out, int out_size) {
    const float* x      = (const float*)d_in[0];
    const float* gate_w = (const float*)d_in[1];
    const float* gate_b = (const float*)d_in[2];
    const float* w1     = (const float*)d_in[3];
    const float* b1     = (const float*)d_in[4];
    const float* w2     = (const float*)d_in[5];
    const float* b2     = (const float*)d_in[6];
    float* out = (float*)d_out;

    cudaFuncSetAttribute(gemm_wmma_kernel<IN_DIM, true>,
                         cudaFuncAttributeMaxDynamicSharedMemorySize, SMEM_DYN);
    cudaFuncSetAttribute(gemm_wmma_kernel<PROJ, false>,
                         cudaFuncAttributeMaxDynamicSharedMemorySize, SMEM_DYN);

    gating_kernel<<<TT / 8, 256>>>(x, gate_w, gate_b);
    fsplit_kernel<<<((size_t)NE * IN_DIM * PROJ / 4) / 256, 256>>>(w1, 1);
    fsplit_kernel<<<((size_t)NE * PROJ * OUT_DIM / 4) / 256, 256>>>(w2, 2);
    bucketA_kernel<<<NBUCK, 256>>>();
    bucketB_kernel<<<1, 256>>>();
    bucketC_kernel<<<NBUCK, 256>>>();
    zero_kernel<<<(TT * (OUT_DIM / 4)) / 256, 256>>>(out);
    gemm_wmma_kernel<IN_DIM, true><<<dim3(MAXTILES, PROJ / 128), 256, SMEM_DYN>>>(b1, out);
    gemm_wmma_kernel<PROJ, false><<<dim3(MAXTILES, OUT_DIM / 128), 256, SMEM_DYN>>>(b2, out);
}

// round 15
// speedup vs baseline: 1.5084x; 1.0829x over previous
#include <cuda_runtime.h>
#include <cuda_bf16.h>
#include <mma.h>
#include <math.h>
#include <stdint.h>

using namespace nvcuda;

#define TT 8192
#define IN_DIM 2048
#define OUT_DIM 2048
#define PROJ 512
#define NE 8
#define NSLOT (TT * 2)
#define PADROWS (NSLOT + NE * 128)   // 17408
#define MAXTILES (PADROWS / 128)     // 136
#define NBUCK 64                     // bucket blocks (64*256 == NSLOT)

#define APAD 24     // sA row stride (elements)
#define BPAD 136    // sB row stride (elements)
// dynamic smem stage layout (bytes)
#define OFF_AL 6144
#define OFF_BH 12288
#define OFF_BL 16640
#define STG 20992
#define NSTAGE 3
#define SOFF_TOK (NSTAGE * STG)          // 62976
#define SOFF_BIAS (SOFF_TOK + 512)
#define SMEM_DYN (SOFF_BIAS + 512)       // 64000

// ---------------- device scratch ----------------
__device__ __align__(16) int   g_route_e[NSLOT];
__device__ __align__(16) float g_route_w[NSLOT];
__device__ __align__(16) int   g_bucket_slot[PADROWS];
__device__ __align__(16) int   g_pos[NSLOT];
__device__ __align__(16) int   g_tile_expert[MAXTILES];
__device__ __align__(16) int   g_tile_rowbase[MAXTILES];
__device__ __align__(16) int   g_localpos[NSLOT];
__device__ __align__(16) int   g_hist[NBUCK][8];
__device__ __align__(16) int   g_blockstart[NBUCK][8];
__device__ __align__(16) __nv_bfloat16 g_x_h[(size_t)TT * IN_DIM];
__device__ __align__(16) __nv_bfloat16 g_x_l[(size_t)TT * IN_DIM];
__device__ __align__(16) __nv_bfloat16 g_w1_h[(size_t)NE * IN_DIM * PROJ];
__device__ __align__(16) __nv_bfloat16 g_w1_l[(size_t)NE * IN_DIM * PROJ];
__device__ __align__(16) __nv_bfloat16 g_w2_h[(size_t)NE * PROJ * OUT_DIM];
__device__ __align__(16) __nv_bfloat16 g_w2_l[(size_t)NE * PROJ * OUT_DIM];
__device__ __align__(16) __nv_bfloat16 g_Hh[(size_t)PADROWS * PROJ];
__device__ __align__(16) __nv_bfloat16 g_Hl[(size_t)PADROWS * PROJ];
__device__ __align__(16) float g_Y[(size_t)PADROWS * OUT_DIM];

// ---------------- helpers ----------------
__device__ __forceinline__ void split2(float a, float b, uint32_t& h, uint32_t& l) {
    __nv_bfloat16 ah = __float2bfloat16(a), bh = __float2bfloat16(b);
    __nv_bfloat16 al = __float2bfloat16(a - __bfloat162float(ah));
    __nv_bfloat16 bl = __float2bfloat16(b - __bfloat162float(bh));
    h = (uint32_t)__bfloat16_as_ushort(ah) | ((uint32_t)__bfloat16_as_ushort(bh) << 16);
    l = (uint32_t)__bfloat16_as_ushort(al) | ((uint32_t)__bfloat16_as_ushort(bl) << 16);
}
__device__ __forceinline__ float gelu_f(float v) {
    const float c = 0.7978845608028654f;
    return 0.5f * v * (1.0f + tanhf(c * (v + 0.044715f * v * v * v)));
}
__device__ __forceinline__ uint32_t smem_u32(const void* p) {
    uint32_t a;
    asm("{ .reg .u64 t; cvta.to.shared.u64 t, %1; cvt.u32.u64 %0, t; }" : "=r"(a) : "l"(p));
    return a;
}
#define CP_ASYNC(dst, src, sz) \
    asm volatile("cp.async.cg.shared.global [%0], [%1], 16, %2;" \
                 :: "r"(dst), "l"(src), "r"(sz) : "memory")
#define CP_COMMIT() asm volatile("cp.async.commit_group;" ::: "memory")
#define CP_WAIT1() asm volatile("cp.async.wait_group 1;" ::: "memory")

// ---------------- 1. gating + x hi/lo split (R10 exact) ----------------
__global__ __launch_bounds__(256) void gating_kernel(
    const float* __restrict__ x, const float* __restrict__ gw,
    const float* __restrict__ gb) {
    int warp = threadIdx.x >> 5, lane = threadIdx.x & 31;
    int t = blockIdx.x * 8 + warp;
    const float* xr = x + (size_t)t * IN_DIM;
    __nv_bfloat16* xh = g_x_h + (size_t)t * IN_DIM;
    __nv_bfloat16* xl = g_x_l + (size_t)t * IN_DIM;
    float acc[8] = {};
    for (int i = lane; i < IN_DIM; i += 32) {
        float xv = xr[i];
        __nv_bfloat16 hh = __float2bfloat16(xv);
        xh[i] = hh;
        xl[i] = __float2bfloat16(xv - __bfloat162float(hh));
        const float4* g4 = (const float4*)(gw + (size_t)i * NE);
        float4 g0 = g4[0], g1 = g4[1];
        acc[0] += xv * g0.x; acc[1] += xv * g0.y; acc[2] += xv * g0.z; acc[3] += xv * g0.w;
        acc[4] += xv * g1.x; acc[5] += xv * g1.y; acc[6] += xv * g1.z; acc[7] += xv * g1.w;
    }
#pragma unroll
    for (int o = 16; o > 0; o >>= 1)
#pragma unroll
        for (int e = 0; e < 8; e++) acc[e] += __shfl_xor_sync(0xffffffffu, acc[e], o);
    if (lane == 0) {
        const float INV = 0.022097086912079608f;
        float l[8], m = -1e30f;
#pragma unroll
        for (int e = 0; e < 8; e++) { l[e] = (acc[e] + gb[e]) * INV; m = fmaxf(m, l[e]); }
        float p[8], s = 0.f;
#pragma unroll
        for (int e = 0; e < 8; e++) { p[e] = expf(l[e] - m); s += p[e]; }
        int i1 = 0;
#pragma unroll
        for (int e = 1; e < 8; e++) if (l[e] > l[i1]) i1 = e;
        int i2 = (i1 == 0) ? 1 : 0;
#pragma unroll
        for (int e = 0; e < 8; e++) if (e != i1 && l[e] > l[i2]) i2 = e;
        float inv_s = 1.f / s;
        g_route_e[2 * t] = i1;     g_route_w[2 * t] = p[i1] * inv_s;
        g_route_e[2 * t + 1] = i2; g_route_w[2 * t + 1] = p[i2] * inv_s;
    }
}

// ---------------- 2a. bucket histogram + local ranks (64 CTAs) ----------------
__global__ __launch_bounds__(256) void bucketA_kernel() {
    __shared__ int wcnt[8][8];    // [warp][expert]
    __shared__ int wbase[8][8];
    const int tid = threadIdx.x, lane = tid & 31, warp = tid >> 5;
    const int b = blockIdx.x;
    const int s = b * 256 + tid;
    for (int i = b * 256 + tid; i < PADROWS; i += NBUCK * 256) g_bucket_slot[i] = -1;
    const int e = g_route_e[s];
    int myrank = 0;
#pragma unroll
    for (int q = 0; q < 8; q++) {
        unsigned bal = __ballot_sync(0xffffffffu, e == q);
        if (e == q) myrank = __popc(bal & ((1u << lane) - 1u));
        if (lane == q) wcnt[warp][q] = __popc(bal);
    }
    __syncthreads();
    if (tid < 8) {
        int ee = tid, r = 0;
#pragma unroll
        for (int w = 0; w < 8; w++) { wbase[w][ee] = r; r += wcnt[w][ee]; }
        g_hist[b][ee] = r;
    }
    __syncthreads();
    g_localpos[s] = wbase[warp][e] + myrank;
}

// ---------------- 2b. cross-block scan + tile table (1 CTA) ----------------
__global__ __launch_bounds__(256) void bucketB_kernel() {
    __shared__ int pre[NBUCK][8];
    __shared__ int tot[8];
    __shared__ int base[8];
    __shared__ int tilebase[9];
    const int tid = threadIdx.x, lane = tid & 31, warp = tid >> 5;
    {
        const int q = warp;   // 8 warps, one expert each
        int carry = 0;
#pragma unroll
        for (int c = 0; c < NBUCK / 32; c++) {
            int v = g_hist[c * 32 + lane][q];
            int s = v;
#pragma unroll
            for (int o = 1; o < 32; o <<= 1) {
                int n = __shfl_up_sync(0xffffffffu, s, o);
                if (lane >= o) s += n;
            }
            pre[c * 32 + lane][q] = carry + s - v;
            carry += __shfl_sync(0xffffffffu, s, 31);
        }
        if (lane == 0) tot[q] = carry;
    }
    __syncthreads();
    if (tid == 0) {
        int p = 0, tb = 0;
        for (int e = 0; e < 8; e++) {
            base[e] = p;
            tilebase[e] = tb;
            int nt = (tot[e] + 127) >> 7;
            tb += nt;
            p += nt * 128;
        }
        tilebase[8] = tb;
    }
    __syncthreads();
    for (int idx = tid; idx < NBUCK * 8; idx += 256) {
        int b = idx >> 3, q = idx & 7;
        g_blockstart[b][q] = base[q] + pre[b][q];
    }
    for (int i = tid; i < MAXTILES; i += 256) {
        int e = -1;
#pragma unroll
        for (int q = 0; q < 8; q++)
            if (i >= tilebase[q] && i < tilebase[q + 1]) e = q;
        g_tile_expert[i] = e;
        g_tile_rowbase[i] = (e >= 0) ? base[e] + (i - tilebase[e]) * 128 : 0;
    }
}

// ---------------- 2c. scatter (64 CTAs) ----------------
__global__ __launch_bounds__(256) void bucketC_kernel() {
    const int s = blockIdx.x * 256 + threadIdx.x;
    const int e = g_route_e[s];
    const int p = g_blockstart[blockIdx.x][e] + g_localpos[s];
    g_bucket_slot[p] = s;
    g_pos[s] = p;
}

// ---------------- weight fp32 -> bf16 hi/lo split (R10 exact) ----------------
__global__ __launch_bounds__(256) void fsplit_kernel(const float* __restrict__ src, int which) {
    __nv_bfloat16 *dh, *dl;
    if (which == 1) { dh = g_w1_h; dl = g_w1_l; }
    else            { dh = g_w2_h; dl = g_w2_l; }
    size_t i = (size_t)blockIdx.x * 256 + threadIdx.x;   // per 4 floats
    float4 v = ((const float4*)src)[i];
    uint32_t h0, l0, h1, l1;
    split2(v.x, v.y, h0, l0);
    split2(v.z, v.w, h1, l1);
    ((uint2*)dh)[i] = make_uint2(h0, h1);
    ((uint2*)dl)[i] = make_uint2(l0, l1);
}

// ---------------- wmma GEMM: 8 warps, 32x64 warp tile, 3-stage cp.async (R10 exact) ----------------
template <int KTOT, bool IS_G1>
__global__ __launch_bounds__(256, 2) void gemm_wmma_kernel(const float* __restrict__ bias) {
    constexpr int NC = KTOT / 16;
    constexpr int NDIM = IS_G1 ? PROJ : OUT_DIM;
    extern __shared__ __align__(16) char smx[];
    int* tokS = (int*)(smx + SOFF_TOK);
    float* biasS = (float*)(smx + SOFF_BIAS);

    const int e = g_tile_expert[blockIdx.x];
    if (e < 0) return;
    const int rowbase = g_tile_rowbase[blockIdx.x];
    const int n0 = blockIdx.y * 128;
    const int tid = threadIdx.x, lane = tid & 31, warp = tid >> 5;
    const int wm = warp >> 1, wn = warp & 1;   // warp tile: 32m x 64n
    const uint32_t sbase = smem_u32(smx);

    if (tid < 128) {
        int slot = g_bucket_slot[rowbase + tid];
        tokS[tid] = IS_G1 ? (slot >= 0 ? (slot >> 1) : -1) : slot;
        biasS[tid] = bias[(size_t)e * NDIM + n0 + tid];
    }
    __syncthreads();

    // loader geometry
    const int lr = tid >> 1, lc8 = (tid & 1) * 8;
    const int bk = tid >> 4, bn8 = (tid & 15) * 8;
    const __nv_bfloat16 *pAh, *pAl;
    uint32_t valA = 16;
    if (IS_G1) {
        int tok = tokS[lr];
        if (tok < 0) { valA = 0; tok = 0; }
        pAh = g_x_h + (size_t)tok * IN_DIM + lc8;
        pAl = g_x_l + (size_t)tok * IN_DIM + lc8;
    } else {
        pAh = g_Hh + (size_t)(rowbase + lr) * PROJ + lc8;
        pAl = g_Hl + (size_t)(rowbase + lr) * PROJ + lc8;
    }
    const __nv_bfloat16* Wh = IS_G1 ? g_w1_h : g_w2_h;
    const __nv_bfloat16* Wl = IS_G1 ? g_w1_l : g_w2_l;
    const __nv_bfloat16* pBh = Wh + ((size_t)e * KTOT + bk) * NDIM + n0 + bn8;
    const __nv_bfloat16* pBl = Wl + ((size_t)e * KTOT + bk) * NDIM + n0 + bn8;

    const uint32_t offA = (uint32_t)(lr * APAD + lc8) * 2;
    const uint32_t offB = (uint32_t)(bk * BPAD + bn8) * 2;

#define ISSUE(kidx)                                                         \
    do {                                                                    \
        const uint32_t _s = sbase + (uint32_t)((kidx) % 3) * STG;           \
        const size_t _ka = (size_t)(kidx) * 16;                             \
        CP_ASYNC(_s + offA, pAh + _ka, valA);                               \
        CP_ASYNC(_s + OFF_AL + offA, pAl + _ka, valA);                      \
        CP_ASYNC(_s + OFF_BH + offB, pBh + _ka * NDIM, 16);                 \
        CP_ASYNC(_s + OFF_BL + offB, pBl + _ka * NDIM, 16);                 \
        CP_COMMIT();                                                        \
    } while (0)

    wmma::fragment<wmma::accumulator, 16, 16, 16, float> facc[2][4];
#pragma unroll
    for (int mi = 0; mi < 2; mi++)
#pragma unroll
        for (int ng = 0; ng < 4; ng++) wmma::fill_fragment(facc[mi][ng], 0.f);

    ISSUE(0);
    ISSUE(1);

#pragma unroll 1
    for (int k = 0; k < NC; k++) {
        CP_WAIT1();               // stage k done (only stage k+1 may remain in flight)
        __syncthreads();          // everyone waited; readers of buffer (k+2)%3 are done
        if (k + 2 < NC) { ISSUE(k + 2); } else { CP_COMMIT(); }

        char* bufp = smx + (k % 3) * STG;
        wmma::fragment<wmma::matrix_a, 16, 16, 16, __nv_bfloat16, wmma::row_major> fah[2], fal[2];
#pragma unroll
        for (int mi = 0; mi < 2; mi++) {
            const int ar = wm * 32 + mi * 16;
            wmma::load_matrix_sync(fah[mi], (__nv_bfloat16*)bufp + ar * APAD, APAD);
            wmma::load_matrix_sync(fal[mi], (__nv_bfloat16*)(bufp + OFF_AL) + ar * APAD, APAD);
        }
#pragma unroll
        for (int ng = 0; ng < 4; ng++) {
            wmma::fragment<wmma::matrix_b, 16, 16, 16, __nv_bfloat16, wmma::row_major> fbh, fbl;
            const int bc = wn * 64 + ng * 16;
            wmma::load_matrix_sync(fbh, (__nv_bfloat16*)(bufp + OFF_BH) + bc, BPAD);
            wmma::load_matrix_sync(fbl, (__nv_bfloat16*)(bufp + OFF_BL) + bc, BPAD);
#pragma unroll
            for (int mi = 0; mi < 2; mi++) {
                wmma::mma_sync(facc[mi][ng], fah[mi], fbh, facc[mi][ng]);
                wmma::mma_sync(facc[mi][ng], fal[mi], fbh, facc[mi][ng]);
                wmma::mma_sync(facc[mi][ng], fah[mi], fbl, facc[mi][ng]);
            }
        }
    }

    // ---- epilogue: reuse smem as per-warp patch buffer ----
    __syncthreads();
    float* pw = (float*)smx + warp * 256;
#pragma unroll
    for (int mi = 0; mi < 2; mi++)
#pragma unroll
        for (int ng = 0; ng < 4; ng++) {
            __syncwarp();
            wmma::store_matrix_sync(pw, facc[mi][ng], 16, wmma::mem_row_major);
            __syncwarp();
            const int r = lane >> 1;               // 0..15
            const int c0 = (lane & 1) * 8;         // 0 or 8
            const int mloc = wm * 32 + mi * 16 + r;
            const size_t grow = (size_t)rowbase + mloc;
            const int lcol = wn * 64 + ng * 16 + c0;
            if (IS_G1) {
                float v[8];
#pragma unroll
                for (int j = 0; j < 8; j++)
                    v[j] = gelu_f(pw[r * 16 + c0 + j] + biasS[lcol + j]);
                uint32_t h[4], l[4];
#pragma unroll
                for (int q = 0; q < 4; q++) split2(v[2 * q], v[2 * q + 1], h[q], l[q]);
                *(uint4*)(g_Hh + grow * PROJ + n0 + lcol) = make_uint4(h[0], h[1], h[2], h[3]);
                *(uint4*)(g_Hl + grow * PROJ + n0 + lcol) = make_uint4(l[0], l[1], l[2], l[3]);
            } else {
                const int slot = tokS[mloc];
                if (slot >= 0) {
                    const float w = g_route_w[slot];
                    float* dst = g_Y + grow * OUT_DIM + n0 + lcol;
#pragma unroll
                    for (int j = 0; j < 8; j++)
                        dst[j] = w * (pw[r * 16 + c0 + j] + biasS[lcol + j]);
                }
            }
        }
#undef ISSUE
}

// ---------------- combine (R10 exact) ----------------
__global__ __launch_bounds__(256) void combine_kernel(float* __restrict__ out) {
    int idx = blockIdx.x * 256 + threadIdx.x;
    int t = idx >> 9;
    int c = idx & 511;
    int p0 = g_pos[2 * t], p1 = g_pos[2 * t + 1];
    float4 a = ((const float4*)(g_Y + (size_t)p0 * OUT_DIM))[c];
    float4 b = ((const float4*)(g_Y + (size_t)p1 * OUT_DIM))[c];
    ((float4*)out)[idx] = make_float4(a.x + b.x, a.y + b.y, a.z + b.z, a.w + b.w);
}

extern "C" void kernel_launch(void* const* d_in, const int* in_sizes, int n_in,
                              void* d_out, int out_size) {
    const float* x      = (const float*)d_in[0];
    const float* gate_w = (const float*)d_in[1];
    const float* gate_b = (const float*)d_in[2];
    const float* w1     = (const float*)d_in[3];
    const float* b1     = (const float*)d_in[4];
    const float* w2     = (const float*)d_in[5];
    const float* b2     = (const float*)d_in[6];
    float* out = (float*)d_out;

    cudaFuncSetAttribute(gemm_wmma_kernel<IN_DIM, true>,
                         cudaFuncAttributeMaxDynamicSharedMemorySize, SMEM_DYN);
    cudaFuncSetAttribute(gemm_wmma_kernel<PROJ, false>,
                         cudaFuncAttributeMaxDynamicSharedMemorySize, SMEM_DYN);

    gating_kernel<<<TT / 8, 256>>>(x, gate_w, gate_b);
    fsplit_kernel<<<((size_t)NE * IN_DIM * PROJ / 4) / 256, 256>>>(w1, 1);
    fsplit_kernel<<<((size_t)NE * PROJ * OUT_DIM / 4) / 256, 256>>>(w2, 2);
    bucketA_kernel<<<NBUCK, 256>>>();
    bucketB_kernel<<<1, 256>>>();
    bucketC_kernel<<<NBUCK, 256>>>();
    gemm_wmma_kernel<IN_DIM, true><<<dim3(MAXTILES, PROJ / 128), 256, SMEM_DYN>>>(b1);
    gemm_wmma_kernel<PROJ, false><<<dim3(MAXTILES, OUT_DIM / 128), 256, SMEM_DYN>>>(b2);
    combine_kernel<<<(TT * (OUT_DIM / 4)) / 256, 256>>>(out);
}

// round 16
// speedup vs baseline: 1.5089x; 1.0003x over previous
#include <cuda_runtime.h>
#include <cuda_bf16.h>
#include <mma.h>
#include <math.h>
#include <stdint.h>

using namespace nvcuda;

#define TT 8192
#define IN_DIM 2048
#define OUT_DIM 2048
#define PROJ 512
#define NE 8
#define NSLOT (TT * 2)
#define PADROWS (NSLOT + NE * 128)   // 17408
#define MAXTILES (PADROWS / 128)     // 136
#define NBUCK 64                     // bucket blocks (64*256 == NSLOT)

#define APAD 24     // sA row stride (elements)
#define BPAD 136    // sB row stride (elements)
// dynamic smem stage layout (bytes)
#define OFF_AL 6144
#define OFF_BH 12288
#define OFF_BL 16640
#define STG 20992
#define NSTAGE 3
#define SOFF_TOK (NSTAGE * STG)          // 62976
#define SOFF_BIAS (SOFF_TOK + 512)
#define SMEM_DYN (SOFF_BIAS + 512)       // 64000

// ---------------- device scratch ----------------
__device__ __align__(16) int   g_route_e[NSLOT];
__device__ __align__(16) float g_route_w[NSLOT];
__device__ __align__(16) int   g_bucket_slot[PADROWS];
__device__ __align__(16) int   g_pos[NSLOT];
__device__ __align__(16) int   g_tile_expert[MAXTILES];
__device__ __align__(16) int   g_tile_rowbase[MAXTILES];
__device__ __align__(16) int   g_localpos[NSLOT];
__device__ __align__(16) int   g_hist[NBUCK][8];
__device__ __align__(16) int   g_blockstart[NBUCK][8];
__device__ __align__(16) __nv_bfloat16 g_x_h[(size_t)TT * IN_DIM];
__device__ __align__(16) __nv_bfloat16 g_x_l[(size_t)TT * IN_DIM];
__device__ __align__(16) __nv_bfloat16 g_w1_h[(size_t)NE * IN_DIM * PROJ];
__device__ __align__(16) __nv_bfloat16 g_w1_l[(size_t)NE * IN_DIM * PROJ];
__device__ __align__(16) __nv_bfloat16 g_w2_h[(size_t)NE * PROJ * OUT_DIM];
__device__ __align__(16) __nv_bfloat16 g_w2_l[(size_t)NE * PROJ * OUT_DIM];
__device__ __align__(16) __nv_bfloat16 g_Hh[(size_t)PADROWS * PROJ];
__device__ __align__(16) __nv_bfloat16 g_Hl[(size_t)PADROWS * PROJ];
__device__ __align__(16) float g_Y[(size_t)PADROWS * OUT_DIM];

// ---------------- helpers ----------------
__device__ __forceinline__ void split2(float a, float b, uint32_t& h, uint32_t& l) {
    __nv_bfloat16 ah = __float2bfloat16(a), bh = __float2bfloat16(b);
    __nv_bfloat16 al = __float2bfloat16(a - __bfloat162float(ah));
    __nv_bfloat16 bl = __float2bfloat16(b - __bfloat162float(bh));
    h = (uint32_t)__bfloat16_as_ushort(ah) | ((uint32_t)__bfloat16_as_ushort(bh) << 16);
    l = (uint32_t)__bfloat16_as_ushort(al) | ((uint32_t)__bfloat16_as_ushort(bl) << 16);
}
__device__ __forceinline__ float gelu_f(float v) {
    const float c = 0.7978845608028654f;
    return 0.5f * v * (1.0f + tanhf(c * (v + 0.044715f * v * v * v)));
}
__device__ __forceinline__ uint32_t smem_u32(const void* p) {
    uint32_t a;
    asm("{ .reg .u64 t; cvta.to.shared.u64 t, %1; cvt.u32.u64 %0, t; }" : "=r"(a) : "l"(p));
    return a;
}
#define CP_ASYNC(dst, src, sz) \
    asm volatile("cp.async.cg.shared.global [%0], [%1], 16, %2;" \
                 :: "r"(dst), "l"(src), "r"(sz) : "memory")
#define CP_COMMIT() asm volatile("cp.async.commit_group;" ::: "memory")
#define CP_WAIT1() asm volatile("cp.async.wait_group 1;" ::: "memory")

// ---------------- 1. gating + x hi/lo split (R10 exact) ----------------
__global__ __launch_bounds__(256) void gating_kernel(
    const float* __restrict__ x, const float* __restrict__ gw,
    const float* __restrict__ gb) {
    int warp = threadIdx.x >> 5, lane = threadIdx.x & 31;
    int t = blockIdx.x * 8 + warp;
    const float* xr = x + (size_t)t * IN_DIM;
    __nv_bfloat16* xh = g_x_h + (size_t)t * IN_DIM;
    __nv_bfloat16* xl = g_x_l + (size_t)t * IN_DIM;
    float acc[8] = {};
    for (int i = lane; i < IN_DIM; i += 32) {
        float xv = xr[i];
        __nv_bfloat16 hh = __float2bfloat16(xv);
        xh[i] = hh;
        xl[i] = __float2bfloat16(xv - __bfloat162float(hh));
        const float4* g4 = (const float4*)(gw + (size_t)i * NE);
        float4 g0 = g4[0], g1 = g4[1];
        acc[0] += xv * g0.x; acc[1] += xv * g0.y; acc[2] += xv * g0.z; acc[3] += xv * g0.w;
        acc[4] += xv * g1.x; acc[5] += xv * g1.y; acc[6] += xv * g1.z; acc[7] += xv * g1.w;
    }
#pragma unroll
    for (int o = 16; o > 0; o >>= 1)
#pragma unroll
        for (int e = 0; e < 8; e++) acc[e] += __shfl_xor_sync(0xffffffffu, acc[e], o);
    if (lane == 0) {
        const float INV = 0.022097086912079608f;
        float l[8], m = -1e30f;
#pragma unroll
        for (int e = 0; e < 8; e++) { l[e] = (acc[e] + gb[e]) * INV; m = fmaxf(m, l[e]); }
        float p[8], s = 0.f;
#pragma unroll
        for (int e = 0; e < 8; e++) { p[e] = expf(l[e] - m); s += p[e]; }
        int i1 = 0;
#pragma unroll
        for (int e = 1; e < 8; e++) if (l[e] > l[i1]) i1 = e;
        int i2 = (i1 == 0) ? 1 : 0;
#pragma unroll
        for (int e = 0; e < 8; e++) if (e != i1 && l[e] > l[i2]) i2 = e;
        float inv_s = 1.f / s;
        g_route_e[2 * t] = i1;     g_route_w[2 * t] = p[i1] * inv_s;
        g_route_e[2 * t + 1] = i2; g_route_w[2 * t + 1] = p[i2] * inv_s;
    }
}

// ---------------- 2a. bucket histogram + local ranks (64 CTAs) ----------------
__global__ __launch_bounds__(256) void bucketA_kernel() {
    __shared__ int wcnt[8][8];    // [warp][expert]
    __shared__ int wbase[8][8];
    const int tid = threadIdx.x, lane = tid & 31, warp = tid >> 5;
    const int b = blockIdx.x;
    const int s = b * 256 + tid;
    for (int i = b * 256 + tid; i < PADROWS; i += NBUCK * 256) g_bucket_slot[i] = -1;
    const int e = g_route_e[s];
    int myrank = 0;
#pragma unroll
    for (int q = 0; q < 8; q++) {
        unsigned bal = __ballot_sync(0xffffffffu, e == q);
        if (e == q) myrank = __popc(bal & ((1u << lane) - 1u));
        if (lane == q) wcnt[warp][q] = __popc(bal);
    }
    __syncthreads();
    if (tid < 8) {
        int ee = tid, r = 0;
#pragma unroll
        for (int w = 0; w < 8; w++) { wbase[w][ee] = r; r += wcnt[w][ee]; }
        g_hist[b][ee] = r;
    }
    __syncthreads();
    g_localpos[s] = wbase[warp][e] + myrank;
}

// ---------------- 2b. cross-block scan + tile table (1 CTA) ----------------
__global__ __launch_bounds__(256) void bucketB_kernel() {
    __shared__ int pre[NBUCK][8];
    __shared__ int tot[8];
    __shared__ int base[8];
    __shared__ int tilebase[9];
    const int tid = threadIdx.x, lane = tid & 31, warp = tid >> 5;
    {
        const int q = warp;   // 8 warps, one expert each
        int carry = 0;
#pragma unroll
        for (int c = 0; c < NBUCK / 32; c++) {
            int v = g_hist[c * 32 + lane][q];
            int s = v;
#pragma unroll
            for (int o = 1; o < 32; o <<= 1) {
                int n = __shfl_up_sync(0xffffffffu, s, o);
                if (lane >= o) s += n;
            }
            pre[c * 32 + lane][q] = carry + s - v;
            carry += __shfl_sync(0xffffffffu, s, 31);
        }
        if (lane == 0) tot[q] = carry;
    }
    __syncthreads();
    if (tid == 0) {
        int p = 0, tb = 0;
        for (int e = 0; e < 8; e++) {
            base[e] = p;
            tilebase[e] = tb;
            int nt = (tot[e] + 127) >> 7;
            tb += nt;
            p += nt * 128;
        }
        tilebase[8] = tb;
    }
    __syncthreads();
    for (int idx = tid; idx < NBUCK * 8; idx += 256) {
        int b = idx >> 3, q = idx & 7;
        g_blockstart[b][q] = base[q] + pre[b][q];
    }
    for (int i = tid; i < MAXTILES; i += 256) {
        int e = -1;
#pragma unroll
        for (int q = 0; q < 8; q++)
            if (i >= tilebase[q] && i < tilebase[q + 1]) e = q;
        g_tile_expert[i] = e;
        g_tile_rowbase[i] = (e >= 0) ? base[e] + (i - tilebase[e]) * 128 : 0;
    }
}

// ---------------- 2c. scatter (64 CTAs) ----------------
__global__ __launch_bounds__(256) void bucketC_kernel() {
    const int s = blockIdx.x * 256 + threadIdx.x;
    const int e = g_route_e[s];
    const int p = g_blockstart[blockIdx.x][e] + g_localpos[s];
    g_bucket_slot[p] = s;
    g_pos[s] = p;
}

// ---------------- weight fp32 -> bf16 hi/lo split (R10 exact) ----------------
__global__ __launch_bounds__(256) void fsplit_kernel(const float* __restrict__ src, int which) {
    __nv_bfloat16 *dh, *dl;
    if (which == 1) { dh = g_w1_h; dl = g_w1_l; }
    else            { dh = g_w2_h; dl = g_w2_l; }
    size_t i = (size_t)blockIdx.x * 256 + threadIdx.x;   // per 4 floats
    float4 v = ((const float4*)src)[i];
    uint32_t h0, l0, h1, l1;
    split2(v.x, v.y, h0, l0);
    split2(v.z, v.w, h1, l1);
    ((uint2*)dh)[i] = make_uint2(h0, h1);
    ((uint2*)dl)[i] = make_uint2(l0, l1);
}

// ---------------- wmma GEMM: 8 warps, 32x64 warp tile, 3-stage cp.async (R10 core) ----------------
template <int KTOT, bool IS_G1>
__global__ __launch_bounds__(256, 2) void gemm_wmma_kernel(const float* __restrict__ bias) {
    constexpr int NC = KTOT / 16;
    constexpr int NDIM = IS_G1 ? PROJ : OUT_DIM;
    extern __shared__ __align__(16) char smx[];
    int* tokS = (int*)(smx + SOFF_TOK);
    float* biasS = (float*)(smx + SOFF_BIAS);

    const int e = g_tile_expert[blockIdx.x];
    if (e < 0) return;
    const int rowbase = g_tile_rowbase[blockIdx.x];
    const int n0 = blockIdx.y * 128;
    const int tid = threadIdx.x, lane = tid & 31, warp = tid >> 5;
    const int wm = warp >> 1, wn = warp & 1;   // warp tile: 32m x 64n
    const uint32_t sbase = smem_u32(smx);

    if (tid < 128) {
        int slot = g_bucket_slot[rowbase + tid];
        tokS[tid] = IS_G1 ? (slot >= 0 ? (slot >> 1) : -1) : slot;
        biasS[tid] = bias[(size_t)e * NDIM + n0 + tid];
    }
    __syncthreads();

    // loader geometry
    const int lr = tid >> 1, lc8 = (tid & 1) * 8;
    const int bk = tid >> 4, bn8 = (tid & 15) * 8;
    const __nv_bfloat16 *pAh, *pAl;
    uint32_t valA = 16;
    if (IS_G1) {
        int tok = tokS[lr];
        if (tok < 0) { valA = 0; tok = 0; }
        pAh = g_x_h + (size_t)tok * IN_DIM + lc8;
        pAl = g_x_l + (size_t)tok * IN_DIM + lc8;
    } else {
        pAh = g_Hh + (size_t)(rowbase + lr) * PROJ + lc8;
        pAl = g_Hl + (size_t)(rowbase + lr) * PROJ + lc8;
    }
    const __nv_bfloat16* Wh = IS_G1 ? g_w1_h : g_w2_h;
    const __nv_bfloat16* Wl = IS_G1 ? g_w1_l : g_w2_l;
    const __nv_bfloat16* pBh = Wh + ((size_t)e * KTOT + bk) * NDIM + n0 + bn8;
    const __nv_bfloat16* pBl = Wl + ((size_t)e * KTOT + bk) * NDIM + n0 + bn8;

    const uint32_t offA = (uint32_t)(lr * APAD + lc8) * 2;
    const uint32_t offB = (uint32_t)(bk * BPAD + bn8) * 2;

#define ISSUE(kidx)                                                         \
    do {                                                                    \
        const uint32_t _s = sbase + (uint32_t)((kidx) % 3) * STG;           \
        const size_t _ka = (size_t)(kidx) * 16;                             \
        CP_ASYNC(_s + offA, pAh + _ka, valA);                               \
        CP_ASYNC(_s + OFF_AL + offA, pAl + _ka, valA);                      \
        CP_ASYNC(_s + OFF_BH + offB, pBh + _ka * NDIM, 16);                 \
        CP_ASYNC(_s + OFF_BL + offB, pBl + _ka * NDIM, 16);                 \
        CP_COMMIT();                                                        \
    } while (0)

    wmma::fragment<wmma::accumulator, 16, 16, 16, float> facc[2][4];
#pragma unroll
    for (int mi = 0; mi < 2; mi++)
#pragma unroll
        for (int ng = 0; ng < 4; ng++) wmma::fill_fragment(facc[mi][ng], 0.f);

    ISSUE(0);
    ISSUE(1);

#pragma unroll 1
    for (int k = 0; k < NC; k++) {
        CP_WAIT1();               // stage k done (only stage k+1 may remain in flight)
        __syncthreads();          // everyone waited; readers of buffer (k+2)%3 are done
        if (k + 2 < NC) { ISSUE(k + 2); } else { CP_COMMIT(); }

        char* bufp = smx + (k % 3) * STG;
        wmma::fragment<wmma::matrix_a, 16, 16, 16, __nv_bfloat16, wmma::row_major> fah[2], fal[2];
#pragma unroll
        for (int mi = 0; mi < 2; mi++) {
            const int ar = wm * 32 + mi * 16;
            wmma::load_matrix_sync(fah[mi], (__nv_bfloat16*)bufp + ar * APAD, APAD);
            wmma::load_matrix_sync(fal[mi], (__nv_bfloat16*)(bufp + OFF_AL) + ar * APAD, APAD);
        }
#pragma unroll
        for (int ng = 0; ng < 4; ng++) {
            wmma::fragment<wmma::matrix_b, 16, 16, 16, __nv_bfloat16, wmma::row_major> fbh, fbl;
            const int bc = wn * 64 + ng * 16;
            wmma::load_matrix_sync(fbh, (__nv_bfloat16*)(bufp + OFF_BH) + bc, BPAD);
            wmma::load_matrix_sync(fbl, (__nv_bfloat16*)(bufp + OFF_BL) + bc, BPAD);
#pragma unroll
            for (int mi = 0; mi < 2; mi++) {
                wmma::mma_sync(facc[mi][ng], fah[mi], fbh, facc[mi][ng]);
                wmma::mma_sync(facc[mi][ng], fal[mi], fbh, facc[mi][ng]);
                wmma::mma_sync(facc[mi][ng], fah[mi], fbl, facc[mi][ng]);
            }
        }
    }

    // ---- epilogue: reuse smem as per-warp patch buffer ----
    __syncthreads();
    float* pw = (float*)smx + warp * 256;
#pragma unroll
    for (int mi = 0; mi < 2; mi++)
#pragma unroll
        for (int ng = 0; ng < 4; ng++) {
            __syncwarp();
            wmma::store_matrix_sync(pw, facc[mi][ng], 16, wmma::mem_row_major);
            __syncwarp();
            const int r = lane >> 1;               // 0..15
            const int c0 = (lane & 1) * 8;         // 0 or 8
            const int mloc = wm * 32 + mi * 16 + r;
            const size_t grow = (size_t)rowbase + mloc;
            const int lcol = wn * 64 + ng * 16 + c0;
            if (IS_G1) {
                float v[8];
#pragma unroll
                for (int j = 0; j < 8; j++)
                    v[j] = gelu_f(pw[r * 16 + c0 + j] + biasS[lcol + j]);
                uint32_t h[4], l[4];
#pragma unroll
                for (int q = 0; q < 4; q++) split2(v[2 * q], v[2 * q + 1], h[q], l[q]);
                *(uint4*)(g_Hh + grow * PROJ + n0 + lcol) = make_uint4(h[0], h[1], h[2], h[3]);
                *(uint4*)(g_Hl + grow * PROJ + n0 + lcol) = make_uint4(l[0], l[1], l[2], l[3]);
            } else {
                const int slot = tokS[mloc];
                if (slot >= 0) {
                    const float w = g_route_w[slot];
                    float* dst = g_Y + grow * OUT_DIM + n0 + lcol;
                    float4 v0, v1;
                    v0.x = w * (pw[r * 16 + c0 + 0] + biasS[lcol + 0]);
                    v0.y = w * (pw[r * 16 + c0 + 1] + biasS[lcol + 1]);
                    v0.z = w * (pw[r * 16 + c0 + 2] + biasS[lcol + 2]);
                    v0.w = w * (pw[r * 16 + c0 + 3] + biasS[lcol + 3]);
                    v1.x = w * (pw[r * 16 + c0 + 4] + biasS[lcol + 4]);
                    v1.y = w * (pw[r * 16 + c0 + 5] + biasS[lcol + 5]);
                    v1.z = w * (pw[r * 16 + c0 + 6] + biasS[lcol + 6]);
                    v1.w = w * (pw[r * 16 + c0 + 7] + biasS[lcol + 7]);
                    __stcs((float4*)dst, v0);        // streaming: Y is read-once
                    __stcs((float4*)(dst + 4), v1);
                }
            }
        }
#undef ISSUE
}

// ---------------- combine: streaming loads/stores + 2-chunk ILP ----------------
__global__ __launch_bounds__(256) void combine_kernel(float* __restrict__ out) {
    // each thread handles 2 float4 chunks, 512 elements apart (same token)
    int base = blockIdx.x * 512 + threadIdx.x;   // over TT * (OUT_DIM/4) / 2 blocks
    int t = base >> 9;                            // 512 chunks per token; thread pair covers c and c+256
    int c = base & 255;
    const int p0 = g_pos[2 * t], p1 = g_pos[2 * t + 1];
    const float4* y0 = (const float4*)(g_Y + (size_t)p0 * OUT_DIM);
    const float4* y1 = (const float4*)(g_Y + (size_t)p1 * OUT_DIM);
    float4 a0 = __ldcs(y0 + c);
    float4 b0 = __ldcs(y1 + c);
    float4 a1 = __ldcs(y0 + c + 256);
    float4 b1 = __ldcs(y1 + c + 256);
    float4* o = (float4*)out + ((size_t)t << 9);
    __stcs(o + c, make_float4(a0.x + b0.x, a0.y + b0.y, a0.z + b0.z, a0.w + b0.w));
    __stcs(o + c + 256, make_float4(a1.x + b1.x, a1.y + b1.y, a1.z + b1.z, a1.w + b1.w));
}

extern "C" void kernel_launch(void* const* d_in, const int* in_sizes, int n_in,
                              void* d_out, int out_size) {
    const float* x      = (const float*)d_in[0];
    const float* gate_w = (const float*)d_in[1];
    const float* gate_b = (const float*)d_in[2];
    const float* w1     = (const float*)d_in[3];
    const float* b1     = (const float*)d_in[4];
    const float* w2     = (const float*)d_in[5];
    const float* b2     = (const float*)d_in[6];
    float* out = (float*)d_out;

    cudaFuncSetAttribute(gemm_wmma_kernel<IN_DIM, true>,
                         cudaFuncAttributeMaxDynamicSharedMemorySize, SMEM_DYN);
    cudaFuncSetAttribute(gemm_wmma_kernel<PROJ, false>,
                         cudaFuncAttributeMaxDynamicSharedMemorySize, SMEM_DYN);

    gating_kernel<<<TT / 8, 256>>>(x, gate_w, gate_b);
    fsplit_kernel<<<((size_t)NE * IN_DIM * PROJ / 4) / 256, 256>>>(w1, 1);
    fsplit_kernel<<<((size_t)NE * PROJ * OUT_DIM / 4) / 256, 256>>>(w2, 2);
    bucketA_kernel<<<NBUCK, 256>>>();
    bucketB_kernel<<<1, 256>>>();
    bucketC_kernel<<<NBUCK, 256>>>();
    gemm_wmma_kernel<IN_DIM, true><<<dim3(MAXTILES, PROJ / 128), 256, SMEM_DYN>>>(b1);
    gemm_wmma_kernel<PROJ, false><<<dim3(MAXTILES, OUT_DIM / 128), 256, SMEM_DYN>>>(b2);
    combine_kernel<<<(TT * (OUT_DIM / 4)) / 512, 256>>>(out);
}

// round 17
// speedup vs baseline: 1.5192x; 1.0068x over previous
#include <cuda_runtime.h>
#include <cuda_bf16.h>
#include <mma.h>
#include <math.h>
#include <stdint.h>

using namespace nvcuda;

#define TT 8192
#define IN_DIM 2048
#define OUT_DIM 2048
#define PROJ 512
#define NE 8
#define NSLOT (TT * 2)
#define PADROWS (NSLOT + NE * 128)   // 17408
#define MAXTILES (PADROWS / 128)     // 136
#define NBUCK 64                     // bucket blocks (64*256 == NSLOT)

#define APAD 24     // sA row stride (elements)
#define BPAD 136    // sB row stride (elements)
// dynamic smem stage layout (bytes)
#define OFF_AL 6144
#define OFF_BH 12288
#define OFF_BL 16640
#define STG 20992
#define NSTAGE 3
#define SOFF_TOK (NSTAGE * STG)          // 62976
#define SOFF_BIAS (SOFF_TOK + 512)
#define SMEM_DYN (SOFF_BIAS + 512)       // 64000

// prep kernel block partition
#define GATE_BLOCKS (TT / 8)                                   // 1024
#define W1_BLOCKS ((int)((size_t)NE * IN_DIM * PROJ / 4 / 256))  // 8192
#define W2_BLOCKS ((int)((size_t)NE * PROJ * OUT_DIM / 4 / 256)) // 8192

// ---------------- device scratch ----------------
__device__ __align__(16) int   g_route_e[NSLOT];
__device__ __align__(16) float g_route_w[NSLOT];
__device__ __align__(16) int   g_bucket_slot[PADROWS];
__device__ __align__(16) int   g_pos[NSLOT];
__device__ __align__(16) int   g_tile_expert[MAXTILES];
__device__ __align__(16) int   g_tile_rowbase[MAXTILES];
__device__ __align__(16) int   g_localpos[NSLOT];
__device__ __align__(16) int   g_hist[NBUCK][8];
__device__ __align__(16) int   g_blockstart[NBUCK][8];
__device__ __align__(16) __nv_bfloat16 g_x_h[(size_t)TT * IN_DIM];
__device__ __align__(16) __nv_bfloat16 g_x_l[(size_t)TT * IN_DIM];
__device__ __align__(16) __nv_bfloat16 g_w1_h[(size_t)NE * IN_DIM * PROJ];
__device__ __align__(16) __nv_bfloat16 g_w1_l[(size_t)NE * IN_DIM * PROJ];
__device__ __align__(16) __nv_bfloat16 g_w2_h[(size_t)NE * PROJ * OUT_DIM];
__device__ __align__(16) __nv_bfloat16 g_w2_l[(size_t)NE * PROJ * OUT_DIM];
__device__ __align__(16) __nv_bfloat16 g_Hh[(size_t)PADROWS * PROJ];
__device__ __align__(16) __nv_bfloat16 g_Hl[(size_t)PADROWS * PROJ];
__device__ __align__(16) float g_Y[(size_t)PADROWS * OUT_DIM];

// ---------------- helpers ----------------
__device__ __forceinline__ void split2(float a, float b, uint32_t& h, uint32_t& l) {
    __nv_bfloat16 ah = __float2bfloat16(a), bh = __float2bfloat16(b);
    __nv_bfloat16 al = __float2bfloat16(a - __bfloat162float(ah));
    __nv_bfloat16 bl = __float2bfloat16(b - __bfloat162float(bh));
    h = (uint32_t)__bfloat16_as_ushort(ah) | ((uint32_t)__bfloat16_as_ushort(bh) << 16);
    l = (uint32_t)__bfloat16_as_ushort(al) | ((uint32_t)__bfloat16_as_ushort(bl) << 16);
}
__device__ __forceinline__ float gelu_f(float v) {
    const float c = 0.7978845608028654f;
    return 0.5f * v * (1.0f + tanhf(c * (v + 0.044715f * v * v * v)));
}
__device__ __forceinline__ uint32_t smem_u32(const void* p) {
    uint32_t a;
    asm("{ .reg .u64 t; cvta.to.shared.u64 t, %1; cvt.u32.u64 %0, t; }" : "=r"(a) : "l"(p));
    return a;
}
#define CP_ASYNC(dst, src, sz) \
    asm volatile("cp.async.cg.shared.global [%0], [%1], 16, %2;" \
                 :: "r"(dst), "l"(src), "r"(sz) : "memory")
#define CP_COMMIT() asm volatile("cp.async.commit_group;" ::: "memory")
#define CP_WAIT1() asm volatile("cp.async.wait_group 1;" ::: "memory")

// ---------------- 1. fused prep: gating+xsplit (blocks<1024) | w1 split | w2 split ----------------
__global__ __launch_bounds__(256) void prep_kernel(
    const float* __restrict__ x, const float* __restrict__ gw,
    const float* __restrict__ gb, const float* __restrict__ w1,
    const float* __restrict__ w2) {
    const int b = blockIdx.x;
    if (b < GATE_BLOCKS) {
        // ---- gating + x hi/lo split (R10-exact inner code) ----
        int warp = threadIdx.x >> 5, lane = threadIdx.x & 31;
        int t = b * 8 + warp;
        const float* xr = x + (size_t)t * IN_DIM;
        __nv_bfloat16* xh = g_x_h + (size_t)t * IN_DIM;
        __nv_bfloat16* xl = g_x_l + (size_t)t * IN_DIM;
        float acc[8] = {};
        for (int i = lane; i < IN_DIM; i += 32) {
            float xv = xr[i];
            __nv_bfloat16 hh = __float2bfloat16(xv);
            xh[i] = hh;
            xl[i] = __float2bfloat16(xv - __bfloat162float(hh));
            const float4* g4 = (const float4*)(gw + (size_t)i * NE);
            float4 g0 = g4[0], g1 = g4[1];
            acc[0] += xv * g0.x; acc[1] += xv * g0.y; acc[2] += xv * g0.z; acc[3] += xv * g0.w;
            acc[4] += xv * g1.x; acc[5] += xv * g1.y; acc[6] += xv * g1.z; acc[7] += xv * g1.w;
        }
#pragma unroll
        for (int o = 16; o > 0; o >>= 1)
#pragma unroll
            for (int e = 0; e < 8; e++) acc[e] += __shfl_xor_sync(0xffffffffu, acc[e], o);
        if (lane == 0) {
            const float INV = 0.022097086912079608f;
            float l[8], m = -1e30f;
#pragma unroll
            for (int e = 0; e < 8; e++) { l[e] = (acc[e] + gb[e]) * INV; m = fmaxf(m, l[e]); }
            float p[8], s = 0.f;
#pragma unroll
            for (int e = 0; e < 8; e++) { p[e] = expf(l[e] - m); s += p[e]; }
            int i1 = 0;
#pragma unroll
            for (int e = 1; e < 8; e++) if (l[e] > l[i1]) i1 = e;
            int i2 = (i1 == 0) ? 1 : 0;
#pragma unroll
            for (int e = 0; e < 8; e++) if (e != i1 && l[e] > l[i2]) i2 = e;
            float inv_s = 1.f / s;
            g_route_e[2 * t] = i1;     g_route_w[2 * t] = p[i1] * inv_s;
            g_route_e[2 * t + 1] = i2; g_route_w[2 * t + 1] = p[i2] * inv_s;
        }
    } else {
        // ---- weight fp32 -> bf16 hi/lo split (R10-exact inner code) ----
        const float* src;
        __nv_bfloat16 *dh, *dl;
        size_t i;
        if (b < GATE_BLOCKS + W1_BLOCKS) {
            src = w1; dh = g_w1_h; dl = g_w1_l;
            i = (size_t)(b - GATE_BLOCKS) * 256 + threadIdx.x;
        } else {
            src = w2; dh = g_w2_h; dl = g_w2_l;
            i = (size_t)(b - GATE_BLOCKS - W1_BLOCKS) * 256 + threadIdx.x;
        }
        float4 v = ((const float4*)src)[i];
        uint32_t h0, l0, h1, l1;
        split2(v.x, v.y, h0, l0);
        split2(v.z, v.w, h1, l1);
        ((uint2*)dh)[i] = make_uint2(h0, h1);
        ((uint2*)dl)[i] = make_uint2(l0, l1);
    }
}

// ---------------- 2a. bucket histogram + local ranks (64 CTAs) ----------------
__global__ __launch_bounds__(256) void bucketA_kernel() {
    __shared__ int wcnt[8][8];    // [warp][expert]
    __shared__ int wbase[8][8];
    const int tid = threadIdx.x, lane = tid & 31, warp = tid >> 5;
    const int b = blockIdx.x;
    const int s = b * 256 + tid;
    for (int i = b * 256 + tid; i < PADROWS; i += NBUCK * 256) g_bucket_slot[i] = -1;
    const int e = g_route_e[s];
    int myrank = 0;
#pragma unroll
    for (int q = 0; q < 8; q++) {
        unsigned bal = __ballot_sync(0xffffffffu, e == q);
        if (e == q) myrank = __popc(bal & ((1u << lane) - 1u));
        if (lane == q) wcnt[warp][q] = __popc(bal);
    }
    __syncthreads();
    if (tid < 8) {
        int ee = tid, r = 0;
#pragma unroll
        for (int w = 0; w < 8; w++) { wbase[w][ee] = r; r += wcnt[w][ee]; }
        g_hist[b][ee] = r;
    }
    __syncthreads();
    g_localpos[s] = wbase[warp][e] + myrank;
}

// ---------------- 2b. cross-block scan + tile table (1 CTA) ----------------
__global__ __launch_bounds__(256) void bucketB_kernel() {
    __shared__ int pre[NBUCK][8];
    __shared__ int tot[8];
    __shared__ int base[8];
    __shared__ int tilebase[9];
    const int tid = threadIdx.x, lane = tid & 31, warp = tid >> 5;
    {
        const int q = warp;   // 8 warps, one expert each
        int carry = 0;
#pragma unroll
        for (int c = 0; c < NBUCK / 32; c++) {
            int v = g_hist[c * 32 + lane][q];
            int s = v;
#pragma unroll
            for (int o = 1; o < 32; o <<= 1) {
                int n = __shfl_up_sync(0xffffffffu, s, o);
                if (lane >= o) s += n;
            }
            pre[c * 32 + lane][q] = carry + s - v;
            carry += __shfl_sync(0xffffffffu, s, 31);
        }
        if (lane == 0) tot[q] = carry;
    }
    __syncthreads();
    if (tid == 0) {
        int p = 0, tb = 0;
        for (int e = 0; e < 8; e++) {
            base[e] = p;
            tilebase[e] = tb;
            int nt = (tot[e] + 127) >> 7;
            tb += nt;
            p += nt * 128;
        }
        tilebase[8] = tb;
    }
    __syncthreads();
    for (int idx = tid; idx < NBUCK * 8; idx += 256) {
        int b = idx >> 3, q = idx & 7;
        g_blockstart[b][q] = base[q] + pre[b][q];
    }
    for (int i = tid; i < MAXTILES; i += 256) {
        int e = -1;
#pragma unroll
        for (int q = 0; q < 8; q++)
            if (i >= tilebase[q] && i < tilebase[q + 1]) e = q;
        g_tile_expert[i] = e;
        g_tile_rowbase[i] = (e >= 0) ? base[e] + (i - tilebase[e]) * 128 : 0;
    }
}

// ---------------- 2c. scatter (64 CTAs) ----------------
__global__ __launch_bounds__(256) void bucketC_kernel() {
    const int s = blockIdx.x * 256 + threadIdx.x;
    const int e = g_route_e[s];
    const int p = g_blockstart[blockIdx.x][e] + g_localpos[s];
    g_bucket_slot[p] = s;
    g_pos[s] = p;
}

// ---------------- wmma GEMM: 8 warps, 32x64 warp tile, 3-stage cp.async (R10 core) ----------------
template <int KTOT, bool IS_G1>
__global__ __launch_bounds__(256, 2) void gemm_wmma_kernel(const float* __restrict__ bias) {
    constexpr int NC = KTOT / 16;
    constexpr int NDIM = IS_G1 ? PROJ : OUT_DIM;
    extern __shared__ __align__(16) char smx[];
    int* tokS = (int*)(smx + SOFF_TOK);
    float* biasS = (float*)(smx + SOFF_BIAS);

    const int e = g_tile_expert[blockIdx.x];
    if (e < 0) return;
    const int rowbase = g_tile_rowbase[blockIdx.x];
    const int n0 = blockIdx.y * 128;
    const int tid = threadIdx.x, lane = tid & 31, warp = tid >> 5;
    const int wm = warp >> 1, wn = warp & 1;   // warp tile: 32m x 64n
    const uint32_t sbase = smem_u32(smx);

    if (tid < 128) {
        int slot = g_bucket_slot[rowbase + tid];
        tokS[tid] = IS_G1 ? (slot >= 0 ? (slot >> 1) : -1) : slot;
        biasS[tid] = bias[(size_t)e * NDIM + n0 + tid];
    }
    __syncthreads();

    // loader geometry
    const int lr = tid >> 1, lc8 = (tid & 1) * 8;
    const int bk = tid >> 4, bn8 = (tid & 15) * 8;
    const __nv_bfloat16 *pAh, *pAl;
    uint32_t valA = 16;
    if (IS_G1) {
        int tok = tokS[lr];
        if (tok < 0) { valA = 0; tok = 0; }
        pAh = g_x_h + (size_t)tok * IN_DIM + lc8;
        pAl = g_x_l + (size_t)tok * IN_DIM + lc8;
    } else {
        pAh = g_Hh + (size_t)(rowbase + lr) * PROJ + lc8;
        pAl = g_Hl + (size_t)(rowbase + lr) * PROJ + lc8;
    }
    const __nv_bfloat16* Wh = IS_G1 ? g_w1_h : g_w2_h;
    const __nv_bfloat16* Wl = IS_G1 ? g_w1_l : g_w2_l;
    const __nv_bfloat16* pBh = Wh + ((size_t)e * KTOT + bk) * NDIM + n0 + bn8;
    const __nv_bfloat16* pBl = Wl + ((size_t)e * KTOT + bk) * NDIM + n0 + bn8;

    const uint32_t offA = (uint32_t)(lr * APAD + lc8) * 2;
    const uint32_t offB = (uint32_t)(bk * BPAD + bn8) * 2;

#define ISSUE(kidx)                                                         \
    do {                                                                    \
        const uint32_t _s = sbase + (uint32_t)((kidx) % 3) * STG;           \
        const size_t _ka = (size_t)(kidx) * 16;                             \
        CP_ASYNC(_s + offA, pAh + _ka, valA);                               \
        CP_ASYNC(_s + OFF_AL + offA, pAl + _ka, valA);                      \
        CP_ASYNC(_s + OFF_BH + offB, pBh + _ka * NDIM, 16);                 \
        CP_ASYNC(_s + OFF_BL + offB, pBl + _ka * NDIM, 16);                 \
        CP_COMMIT();                                                        \
    } while (0)

    wmma::fragment<wmma::accumulator, 16, 16, 16, float> facc[2][4];
#pragma unroll
    for (int mi = 0; mi < 2; mi++)
#pragma unroll
        for (int ng = 0; ng < 4; ng++) wmma::fill_fragment(facc[mi][ng], 0.f);

    ISSUE(0);
    ISSUE(1);

#pragma unroll 1
    for (int k = 0; k < NC; k++) {
        CP_WAIT1();               // stage k done (only stage k+1 may remain in flight)
        __syncthreads();          // everyone waited; readers of buffer (k+2)%3 are done
        if (k + 2 < NC) { ISSUE(k + 2); } else { CP_COMMIT(); }

        char* bufp = smx + (k % 3) * STG;
        wmma::fragment<wmma::matrix_a, 16, 16, 16, __nv_bfloat16, wmma::row_major> fah[2], fal[2];
#pragma unroll
        for (int mi = 0; mi < 2; mi++) {
            const int ar = wm * 32 + mi * 16;
            wmma::load_matrix_sync(fah[mi], (__nv_bfloat16*)bufp + ar * APAD, APAD);
            wmma::load_matrix_sync(fal[mi], (__nv_bfloat16*)(bufp + OFF_AL) + ar * APAD, APAD);
        }
#pragma unroll
        for (int ng = 0; ng < 4; ng++) {
            wmma::fragment<wmma::matrix_b, 16, 16, 16, __nv_bfloat16, wmma::row_major> fbh, fbl;
            const int bc = wn * 64 + ng * 16;
            wmma::load_matrix_sync(fbh, (__nv_bfloat16*)(bufp + OFF_BH) + bc, BPAD);
            wmma::load_matrix_sync(fbl, (__nv_bfloat16*)(bufp + OFF_BL) + bc, BPAD);
#pragma unroll
            for (int mi = 0; mi < 2; mi++) {
                wmma::mma_sync(facc[mi][ng], fah[mi], fbh, facc[mi][ng]);
                wmma::mma_sync(facc[mi][ng], fal[mi], fbh, facc[mi][ng]);
                wmma::mma_sync(facc[mi][ng], fah[mi], fbl, facc[mi][ng]);
            }
        }
    }

    // ---- epilogue: reuse smem as per-warp patch buffer ----
    __syncthreads();
    float* pw = (float*)smx + warp * 256;
#pragma unroll
    for (int mi = 0; mi < 2; mi++)
#pragma unroll
        for (int ng = 0; ng < 4; ng++) {
            __syncwarp();
            wmma::store_matrix_sync(pw, facc[mi][ng], 16, wmma::mem_row_major);
            __syncwarp();
            const int r = lane >> 1;               // 0..15
            const int c0 = (lane & 1) * 8;         // 0 or 8
            const int mloc = wm * 32 + mi * 16 + r;
            const size_t grow = (size_t)rowbase + mloc;
            const int lcol = wn * 64 + ng * 16 + c0;
            if (IS_G1) {
                float v[8];
#pragma unroll
                for (int j = 0; j < 8; j++)
                    v[j] = gelu_f(pw[r * 16 + c0 + j] + biasS[lcol + j]);
                uint32_t h[4], l[4];
#pragma unroll
                for (int q = 0; q < 4; q++) split2(v[2 * q], v[2 * q + 1], h[q], l[q]);
                *(uint4*)(g_Hh + grow * PROJ + n0 + lcol) = make_uint4(h[0], h[1], h[2], h[3]);
                *(uint4*)(g_Hl + grow * PROJ + n0 + lcol) = make_uint4(l[0], l[1], l[2], l[3]);
            } else {
                const int slot = tokS[mloc];
                if (slot >= 0) {
                    const float w = g_route_w[slot];
                    float* dst = g_Y + grow * OUT_DIM + n0 + lcol;
                    float4 v0, v1;
                    v0.x = w * (pw[r * 16 + c0 + 0] + biasS[lcol + 0]);
                    v0.y = w * (pw[r * 16 + c0 + 1] + biasS[lcol + 1]);
                    v0.z = w * (pw[r * 16 + c0 + 2] + biasS[lcol + 2]);
                    v0.w = w * (pw[r * 16 + c0 + 3] + biasS[lcol + 3]);
                    v1.x = w * (pw[r * 16 + c0 + 4] + biasS[lcol + 4]);
                    v1.y = w * (pw[r * 16 + c0 + 5] + biasS[lcol + 5]);
                    v1.z = w * (pw[r * 16 + c0 + 6] + biasS[lcol + 6]);
                    v1.w = w * (pw[r * 16 + c0 + 7] + biasS[lcol + 7]);
                    __stcs((float4*)dst, v0);        // streaming: Y is read-once
                    __stcs((float4*)(dst + 4), v1);
                }
            }
        }
#undef ISSUE
}

// ---------------- combine: streaming loads/stores + 2-chunk ILP ----------------
__global__ __launch_bounds__(256) void combine_kernel(float* __restrict__ out) {
    // each thread handles 2 float4 chunks, 512 elements apart (same token)
    int base = blockIdx.x * 512 + threadIdx.x;
    int t = base >> 9;
    int c = base & 255;
    const int p0 = g_pos[2 * t], p1 = g_pos[2 * t + 1];
    const float4* y0 = (const float4*)(g_Y + (size_t)p0 * OUT_DIM);
    const float4* y1 = (const float4*)(g_Y + (size_t)p1 * OUT_DIM);
    float4 a0 = __ldcs(y0 + c);
    float4 b0 = __ldcs(y1 + c);
    float4 a1 = __ldcs(y0 + c + 256);
    float4 b1 = __ldcs(y1 + c + 256);
    float4* o = (float4*)out + ((size_t)t << 9);
    __stcs(o + c, make_float4(a0.x + b0.x, a0.y + b0.y, a0.z + b0.z, a0.w + b0.w));
    __stcs(o + c + 256, make_float4(a1.x + b1.x, a1.y + b1.y, a1.z + b1.z, a1.w + b1.w));
}

extern "C" void kernel_launch(void* const* d_in, const int* in_sizes, int n_in,
                              void* d_out, int out_size) {
    const float* x      = (const float*)d_in[0];
    const float* gate_w = (const float*)d_in[1];
    const float* gate_b = (const float*)d_in[2];
    const float* w1     = (const float*)d_in[3];
    const float* b1     = (const float*)d_in[4];
    const float* w2     = (const float*)d_in[5];
    const float* b2     = (const float*)d_in[6];
    float* out = (float*)d_out;

    cudaFuncSetAttribute(gemm_wmma_kernel<IN_DIM, true>,
                         cudaFuncAttributeMaxDynamicSharedMemorySize, SMEM_DYN);
    cudaFuncSetAttribute(gemm_wmma_kernel<PROJ, false>,
                         cudaFuncAttributeMaxDynamicSharedMemorySize, SMEM_DYN);

    prep_kernel<<<GATE_BLOCKS + W1_BLOCKS + W2_BLOCKS, 256>>>(x, gate_w, gate_b, w1, w2);
    bucketA_kernel<<<NBUCK, 256>>>();
    bucketB_kernel<<<1, 256>>>();
    bucketC_kernel<<<NBUCK, 256>>>();
    gemm_wmma_kernel<IN_DIM, true><<<dim3(MAXTILES, PROJ / 128), 256, SMEM_DYN>>>(b1);
    gemm_wmma_kernel<PROJ, false><<<dim3(MAXTILES, OUT_DIM / 128), 256, SMEM_DYN>>>(b2);
    combine_kernel<<<(TT * (OUT_DIM / 4)) / 512, 256>>>(out);
}